// round 9
// baseline (speedup 1.0000x reference)
#include <cuda_runtime.h>
#include <cuda_fp16.h>
#include <mma.h>
#include <math.h>
#include <stdint.h>

using namespace nvcuda;

#define D_EMB 1024
#define NB 8
#define SQ 577
#define SK 13271
#define SKP 13312      // SK padded to 128
#define NT 104         // SKP / 128 n-tiles
#define ROWP 640       // SQ padded to 128
#define SQP 640        // self-attn K padded
#define LNEPS 1e-5f

// ---------------- scratch (__device__ globals) ------------------------------
__device__ __half g_normX_h[(size_t)NB * SK * D_EMB];   // LN(input) fp16
__device__ float  g_xf     [(size_t)NB * SK * 4];       // normX @ fc1^T
__device__ float  g_normQ  [(size_t)NB * SQ * D_EMB];   // LN(query) fp32
__device__ __half g_normQ_h[(size_t)NB * SQ * D_EMB];
__device__ float  g_part   [(size_t)NB * ROWP * NT * 6];// cross softmax partials
__device__ float  g_cross  [(size_t)NB * SQ * D_EMB];   // MLP out, compact
__device__ __half g_normC_h[(size_t)NB * SQ * D_EMB];
__device__ float  g_S2     [(size_t)NB * ROWP * SQP];
__device__ __half g_P2     [(size_t)NB * ROWP * SQP];
__device__ float  g_self   [(size_t)NB * ROWP * D_EMB];

// ---------------- reductions (blockDim == 256) ------------------------------
__device__ __forceinline__ float block_sum(float v, float* red) {
    #pragma unroll
    for (int o = 16; o > 0; o >>= 1) v += __shfl_xor_sync(0xffffffffu, v, o);
    int w = threadIdx.x >> 5;
    if ((threadIdx.x & 31) == 0) red[w] = v;
    __syncthreads();
    float s = 0.f;
    #pragma unroll
    for (int i = 0; i < 8; i++) s += red[i];
    __syncthreads();
    return s;
}
__device__ __forceinline__ float block_max(float v, float* red) {
    #pragma unroll
    for (int o = 16; o > 0; o >>= 1) v = fmaxf(v, __shfl_xor_sync(0xffffffffu, v, o));
    int w = threadIdx.x >> 5;
    if ((threadIdx.x & 31) == 0) red[w] = v;
    __syncthreads();
    float s = -INFINITY;
    #pragma unroll
    for (int i = 0; i < 8; i++) s = fmaxf(s, red[i]);
    __syncthreads();
    return s;
}

// ---------------- layernorm -> fp16 (+ optional fp32, + optional Xf) --------
__global__ void ln_kernel(const float* __restrict__ in, const float* __restrict__ w,
                          const float* __restrict__ b, __half* __restrict__ out_h,
                          float* __restrict__ out_f,
                          const float* __restrict__ fc1, float* __restrict__ xf) {
    __shared__ float red[8];
    __shared__ float red4[4][8];
    size_t row = blockIdx.x;
    float4 v = ((const float4*)(in + row * D_EMB))[threadIdx.x];
    float mean = block_sum(v.x + v.y + v.z + v.w, red) * (1.f / D_EMB);
    float dx = v.x - mean, dy = v.y - mean, dz = v.z - mean, dw = v.w - mean;
    float var = block_sum(dx*dx + dy*dy + dz*dz + dw*dw, red) * (1.f / D_EMB);
    float inv = rsqrtf(var + LNEPS);
    float4 w4 = ((const float4*)w)[threadIdx.x];
    float4 b4 = ((const float4*)b)[threadIdx.x];
    float ox = dx * inv * w4.x + b4.x;
    float oy = dy * inv * w4.y + b4.y;
    float oz = dz * inv * w4.z + b4.z;
    float ow = dw * inv * w4.w + b4.w;
    __half2 h0 = __floats2half2_rn(ox, oy);
    __half2 h1 = __floats2half2_rn(oz, ow);
    uint2 packed = { *(uint32_t*)&h0, *(uint32_t*)&h1 };
    ((uint2*)(out_h + row * D_EMB))[threadIdx.x] = packed;
    if (out_f) {
        float4 o = { ox, oy, oz, ow };
        ((float4*)(out_f + row * D_EMB))[threadIdx.x] = o;
    }
    if (fc1) {
        #pragma unroll
        for (int h = 0; h < 4; h++) {
            float4 f = ((const float4*)(fc1 + (size_t)h * D_EMB))[threadIdx.x];
            float p = ox * f.x + oy * f.y + oz * f.z + ow * f.w;
            #pragma unroll
            for (int o = 16; o > 0; o >>= 1) p += __shfl_xor_sync(0xffffffffu, p, o);
            if ((threadIdx.x & 31) == 0) red4[h][threadIdx.x >> 5] = p;
        }
        __syncthreads();
        if (threadIdx.x < 4) {
            float s = 0.f;
            #pragma unroll
            for (int i = 0; i < 8; i++) s += red4[threadIdx.x][i];
            xf[row * 4 + threadIdx.x] = s;
        }
    }
}

// ---------------- cp.async helper -------------------------------------------
__device__ __forceinline__ void cp16(void* dst, const void* src, bool pred) {
    uint32_t d = (uint32_t)__cvta_generic_to_shared(dst);
    int sz = pred ? 16 : 0;
    asm volatile("cp.async.cg.shared.global [%0], [%1], 16, %2;\n" :: "r"(d), "l"(src), "r"(sz));
}

// ============================================================================
// Fused QK + partial-softmax (cross path): computes the 128x128 score tile,
// then per-row partials (max, sum e, sum e*xf[4]) -> g_part. No S matrix.
// grid: x = m-tile (5), y = n-tile (104), z = batch.
// ============================================================================
#define QK_SMEM (3 * (128 * 72 + 128 * 72) * 2)     // 110592 B; epilogue reuses it
__global__ __launch_bounds__(256)
void gemm_qk_fused(const __half* __restrict__ A, const __half* __restrict__ B,
                   const float* __restrict__ xf, float* __restrict__ part,
                   int Mreal, int Nreal, float alpha,
                   size_t sA, size_t sB) {
    constexpr int ALD = 72;
    constexpr int ASZ = 128 * ALD;
    constexpr int STAGE = 2 * ASZ;
    constexpr int K = D_EMB;

    extern __shared__ __half smh[];

    A += blockIdx.z * sA;  B += blockIdx.z * sB;
    xf += (size_t)blockIdx.z * SK * 4;
    const int m0 = blockIdx.x * 128, n0 = blockIdx.y * 128;
    const int tid = threadIdx.x, warp = tid >> 5;
    const int wm = warp >> 1, wn = warp & 1;

    wmma::fragment<wmma::accumulator, 16, 16, 16, float> acc[2][4];
    #pragma unroll
    for (int i = 0; i < 2; i++)
        #pragma unroll
        for (int j = 0; j < 4; j++) wmma::fill_fragment(acc[i][j], 0.f);

    auto load_tile = [&](int kt, int bufi) {
        const int k0 = kt * 64;
        __half* as = smh + bufi * STAGE;
        __half* bs = as + ASZ;
        #pragma unroll
        for (int i = 0; i < 4; i++) {
            int idx = tid + i * 256;
            int r = idx >> 3, v = (idx & 7) * 8;
            int gr = m0 + r;
            cp16(as + r * ALD + v, A + (size_t)gr * K + k0 + v, gr < Mreal);
        }
        #pragma unroll
        for (int i = 0; i < 4; i++) {
            int idx = tid + i * 256;
            int r = idx >> 3, v = (idx & 7) * 8;
            int gn = n0 + r;
            cp16(bs + r * ALD + v, B + (size_t)gn * K + k0 + v, gn < Nreal);
        }
        asm volatile("cp.async.commit_group;\n");
    };

    const int KT = K / 64;
    load_tile(0, 0);
    load_tile(1, 1);

    for (int kt = 0; kt < KT; kt++) {
        if (kt + 1 < KT) asm volatile("cp.async.wait_group 1;\n");
        else             asm volatile("cp.async.wait_group 0;\n");
        __syncthreads();
        if (kt + 2 < KT) load_tile(kt + 2, (kt + 2) % 3);

        __half* as = smh + (kt % 3) * STAGE;
        __half* bs = as + ASZ;
        #pragma unroll
        for (int ks = 0; ks < 4; ks++) {
            wmma::fragment<wmma::matrix_a, 16, 16, 16, __half, wmma::row_major> af[2];
            #pragma unroll
            for (int i = 0; i < 2; i++)
                wmma::load_matrix_sync(af[i], as + (wm * 32 + i * 16) * ALD + ks * 16, ALD);
            #pragma unroll
            for (int j = 0; j < 4; j++) {
                wmma::fragment<wmma::matrix_b, 16, 16, 16, __half, wmma::col_major> bf;
                wmma::load_matrix_sync(bf, bs + (wn * 64 + j * 16) * ALD + ks * 16, ALD);
                #pragma unroll
                for (int i = 0; i < 2; i++) wmma::mma_sync(acc[i][j], af[i], bf, acc[i][j]);
            }
        }
    }

    // ---- epilogue: stage scaled scores in smem, reduce per row ----
    __syncthreads();                       // everyone done with stage buffers
    float* sbuf = (float*)smh;             // 128 x 132 (132 = 33*4 elems, 16B mult)
    float* xfs  = sbuf + 128 * 132;        // 128 x 4

    #pragma unroll
    for (int i = 0; i < 2; i++)
        #pragma unroll
        for (int j = 0; j < 4; j++) {
            #pragma unroll
            for (int e = 0; e < 8; e++) acc[i][j].x[e] *= alpha;
            wmma::store_matrix_sync(sbuf + (wm * 32 + i * 16) * 132 + (wn * 64 + j * 16),
                                    acc[i][j], 132, wmma::mem_row_major);
        }
    // xf tile (zero for invalid columns)
    {
        int idx = tid >> 1;                // 128 rows, 2 threads each -> idx dup; use tid<128
        if (tid < 128) {
            int gn = n0 + tid;
            float4 x = make_float4(0.f, 0.f, 0.f, 0.f);
            if (gn < Nreal) x = *(const float4*)(xf + (size_t)gn * 4);
            ((float4*)xfs)[tid] = x;
        }
        (void)idx;
    }
    __syncthreads();

    const int row = tid >> 1, half = tid & 1;
    const int nvalid = min(128, Nreal - n0);
    const float* srow = sbuf + row * 132 + half * 64;
    const int base = half * 64;
    float mx = -INFINITY;
    #pragma unroll 8
    for (int c = 0; c < 64; c++)
        if (base + c < nvalid) mx = fmaxf(mx, srow[c]);
    mx = fmaxf(mx, __shfl_xor_sync(0xffffffffu, mx, 1));

    float se = 0.f, a0 = 0.f, a1 = 0.f, a2 = 0.f, a3 = 0.f;
    #pragma unroll 4
    for (int c = 0; c < 64; c++) {
        int col = base + c;
        if (col < nvalid) {
            float e = __expf(srow[c] - mx);
            se += e;
            float4 x = ((const float4*)xfs)[col];
            a0 += e * x.x; a1 += e * x.y; a2 += e * x.z; a3 += e * x.w;
        }
    }
    se += __shfl_xor_sync(0xffffffffu, se, 1);
    a0 += __shfl_xor_sync(0xffffffffu, a0, 1);
    a1 += __shfl_xor_sync(0xffffffffu, a1, 1);
    a2 += __shfl_xor_sync(0xffffffffu, a2, 1);
    a3 += __shfl_xor_sync(0xffffffffu, a3, 1);

    if (half == 0) {
        float* dst = part + (((size_t)blockIdx.z * ROWP + m0 + row) * NT + blockIdx.y) * 6;
        dst[0] = mx; dst[1] = se; dst[2] = a0; dst[3] = a1; dst[4] = a2; dst[5] = a3;
    }
}

// ---------------- reduce partials + MLP -> cross row ------------------------
__global__ void cross_reduce_mlp(const float* __restrict__ part, const float* __restrict__ b1,
                                 const float* __restrict__ fc2, const float* __restrict__ b2,
                                 float* __restrict__ cross) {
    __shared__ float red[8];
    __shared__ float hh[4];
    int b = blockIdx.x / SQ, r = blockIdx.x % SQ;
    const float* p = part + ((size_t)b * ROWP + r) * NT * 6;
    float m = -INFINITY, s = 0.f, a0 = 0.f, a1 = 0.f, a2 = 0.f, a3 = 0.f;
    if (threadIdx.x < NT) m = p[threadIdx.x * 6];
    float M = block_max(m, red);
    if (threadIdx.x < NT) {
        const float* q = p + threadIdx.x * 6;
        float w = __expf(q[0] - M);
        s  = q[1] * w;
        a0 = q[2] * w; a1 = q[3] * w; a2 = q[4] * w; a3 = q[5] * w;
    }
    s  = block_sum(s,  red);
    a0 = block_sum(a0, red);
    a1 = block_sum(a1, red);
    a2 = block_sum(a2, red);
    a3 = block_sum(a3, red);
    if (threadIdx.x == 0) {
        float inv = 1.f / s;
        const float k = 0.70710678118654752f;
        float p0 = a0 * inv + b1[0];
        float p1 = a1 * inv + b1[1];
        float p2 = a2 * inv + b1[2];
        float p3 = a3 * inv + b1[3];
        hh[0] = 0.5f * p0 * (1.f + erff(p0 * k));
        hh[1] = 0.5f * p1 * (1.f + erff(p1 * k));
        hh[2] = 0.5f * p2 * (1.f + erff(p2 * k));
        hh[3] = 0.5f * p3 * (1.f + erff(p3 * k));
    }
    __syncthreads();
    float h0 = hh[0], h1 = hh[1], h2 = hh[2], h3 = hh[3];
    int d = threadIdx.x * 4;
    float* dst = cross + ((size_t)b * SQ + r) * D_EMB + d;
    float4 o;
    { float4 wv = ((const float4*)fc2)[d + 0]; o.x = h0*wv.x + h1*wv.y + h2*wv.z + h3*wv.w + b2[d + 0]; }
    { float4 wv = ((const float4*)fc2)[d + 1]; o.y = h0*wv.x + h1*wv.y + h2*wv.z + h3*wv.w + b2[d + 1]; }
    { float4 wv = ((const float4*)fc2)[d + 2]; o.z = h0*wv.x + h1*wv.y + h2*wv.z + h3*wv.w + b2[d + 2]; }
    { float4 wv = ((const float4*)fc2)[d + 3]; o.w = h0*wv.x + h1*wv.y + h2*wv.z + h3*wv.w + b2[d + 3]; }
    *(float4*)dst = o;
}

// ---------------- QK GEMM (self path): NT fp16 wmma, 128x128x64 -------------
__global__ __launch_bounds__(256)
void gemm_qk(const __half* __restrict__ A, const __half* __restrict__ B, float* __restrict__ C,
             int Mreal, int Nreal, int K, int ldc,
             size_t sA, size_t sB, size_t sC, float alpha) {
    constexpr int ALD = 72;
    constexpr int ASZ = 128 * ALD;
    constexpr int STAGE = 2 * ASZ;

    extern __shared__ __half smh[];

    A += blockIdx.z * sA;  B += blockIdx.z * sB;  C += blockIdx.z * sC;
    const int m0 = blockIdx.x * 128, n0 = blockIdx.y * 128;
    const int tid = threadIdx.x, warp = tid >> 5;
    const int wm = warp >> 1, wn = warp & 1;

    wmma::fragment<wmma::accumulator, 16, 16, 16, float> acc[2][4];
    #pragma unroll
    for (int i = 0; i < 2; i++)
        #pragma unroll
        for (int j = 0; j < 4; j++) wmma::fill_fragment(acc[i][j], 0.f);

    auto load_tile = [&](int kt, int bufi) {
        const int k0 = kt * 64;
        __half* as = smh + bufi * STAGE;
        __half* bs = as + ASZ;
        #pragma unroll
        for (int i = 0; i < 4; i++) {
            int idx = tid + i * 256;
            int r = idx >> 3, v = (idx & 7) * 8;
            int gr = m0 + r;
            cp16(as + r * ALD + v, A + (size_t)gr * K + k0 + v, gr < Mreal);
        }
        #pragma unroll
        for (int i = 0; i < 4; i++) {
            int idx = tid + i * 256;
            int r = idx >> 3, v = (idx & 7) * 8;
            int gn = n0 + r;
            cp16(bs + r * ALD + v, B + (size_t)gn * K + k0 + v, gn < Nreal);
        }
        asm volatile("cp.async.commit_group;\n");
    };

    const int KT = K / 64;
    load_tile(0, 0);
    if (KT > 1) load_tile(1, 1);

    for (int kt = 0; kt < KT; kt++) {
        if (kt + 1 < KT) asm volatile("cp.async.wait_group 1;\n");
        else             asm volatile("cp.async.wait_group 0;\n");
        __syncthreads();
        if (kt + 2 < KT) load_tile(kt + 2, (kt + 2) % 3);

        __half* as = smh + (kt % 3) * STAGE;
        __half* bs = as + ASZ;
        #pragma unroll
        for (int ks = 0; ks < 4; ks++) {
            wmma::fragment<wmma::matrix_a, 16, 16, 16, __half, wmma::row_major> af[2];
            #pragma unroll
            for (int i = 0; i < 2; i++)
                wmma::load_matrix_sync(af[i], as + (wm * 32 + i * 16) * ALD + ks * 16, ALD);
            #pragma unroll
            for (int j = 0; j < 4; j++) {
                wmma::fragment<wmma::matrix_b, 16, 16, 16, __half, wmma::col_major> bf;
                wmma::load_matrix_sync(bf, bs + (wn * 64 + j * 16) * ALD + ks * 16, ALD);
                #pragma unroll
                for (int i = 0; i < 2; i++) wmma::mma_sync(acc[i][j], af[i], bf, acc[i][j]);
            }
        }
    }

    #pragma unroll
    for (int i = 0; i < 2; i++)
        #pragma unroll
        for (int j = 0; j < 4; j++) {
            #pragma unroll
            for (int e = 0; e < 8; e++) acc[i][j].x[e] *= alpha;
            int rg = m0 + wm * 32 + i * 16, cg = n0 + wn * 64 + j * 16;
            wmma::store_matrix_sync(C + (size_t)rg * ldc + cg, acc[i][j], ldc, wmma::mem_row_major);
        }
}

// ---------------- classic softmax (self path): fp32 in -> fp16 probs --------
__global__ void softmax_kernel(const float* __restrict__ S, __half* __restrict__ P,
                               int n, int np, int sq, int rowp) {
    extern __shared__ float buf[];
    __shared__ float red[8];
    int b = blockIdx.x / sq, r = blockIdx.x % sq;
    const float* src = S + ((size_t)b * rowp + r) * np;
    __half* dst = P + ((size_t)b * rowp + r) * np;
    float m = -INFINITY;
    for (int i = threadIdx.x; i < n; i += 256) { float v = src[i]; buf[i] = v; m = fmaxf(m, v); }
    m = block_max(m, red);
    float s = 0.f;
    for (int i = threadIdx.x; i < n; i += 256) { float e = __expf(buf[i] - m); buf[i] = e; s += e; }
    s = block_sum(s, red);
    float inv = 1.f / s;
    for (int i = threadIdx.x; i < n; i += 256) dst[i] = __float2half_rn(buf[i] * inv);
    for (int i = n + threadIdx.x; i < np; i += 256) dst[i] = __ushort_as_half(0);
}

// ---------------- PV GEMM (self path): NN fp16 wmma, 128x256x32, 4-stage ----
#define PV_SMEM (4 * (128 * 40 + 32 * 264) * 2)
__global__ __launch_bounds__(256)
void gemm_pv(const __half* __restrict__ A, const __half* __restrict__ B, float* __restrict__ C,
             int Mreal, int K, int Kreal, int ldb_n, int ldc,
             size_t sA, size_t sB, size_t sC) {
    constexpr int BN = 256;
    constexpr int ALD = 40;
    constexpr int ASZ = 128 * ALD;
    constexpr int BLDN = BN + 8;
    constexpr int BSZ = 32 * BLDN;
    constexpr int STAGE = ASZ + BSZ;
    constexpr int NS = 4;

    extern __shared__ __half smh[];

    A += blockIdx.z * sA;  B += blockIdx.z * sB;  C += blockIdx.z * sC;
    const int m0 = blockIdx.x * 128, n0 = blockIdx.y * BN;
    const int tid = threadIdx.x, warp = tid >> 5;
    const int wm = warp >> 2, wn = warp & 3;

    wmma::fragment<wmma::accumulator, 16, 16, 16, float> acc[4][4];
    #pragma unroll
    for (int i = 0; i < 4; i++)
        #pragma unroll
        for (int j = 0; j < 4; j++) wmma::fill_fragment(acc[i][j], 0.f);

    auto load_tile = [&](int kt, int bufi) {
        const int k0 = kt * 32;
        __half* as = smh + bufi * STAGE;
        __half* bs = as + ASZ;
        #pragma unroll
        for (int i = 0; i < 2; i++) {
            int idx = tid + i * 256;
            int r = idx >> 2, v = (idx & 3) * 8;
            int gr = m0 + r;
            cp16(as + r * ALD + v, A + (size_t)gr * K + k0 + v, gr < Mreal);
        }
        #pragma unroll
        for (int i = 0; i < 4; i++) {
            int idx = tid + i * 256;
            int kk = idx >> 5, v = (idx & 31) * 8;
            int gk = k0 + kk;
            cp16(bs + kk * BLDN + v, B + (size_t)gk * ldb_n + n0 + v, gk < Kreal);
        }
        asm volatile("cp.async.commit_group;\n");
    };

    const int KT = K / 32;
    load_tile(0, 0);
    load_tile(1, 1);
    load_tile(2, 2);

    for (int kt = 0; kt < KT; kt++) {
        const int pend = KT - kt - 1;
        if (pend >= 2)      asm volatile("cp.async.wait_group 2;\n");
        else if (pend == 1) asm volatile("cp.async.wait_group 1;\n");
        else                asm volatile("cp.async.wait_group 0;\n");
        __syncthreads();
        if (kt + 3 < KT) load_tile(kt + 3, (kt + 3) % NS);

        __half* as = smh + (kt % NS) * STAGE;
        __half* bs = as + ASZ;
        #pragma unroll
        for (int ks = 0; ks < 2; ks++) {
            wmma::fragment<wmma::matrix_a, 16, 16, 16, __half, wmma::row_major> af[4];
            #pragma unroll
            for (int i = 0; i < 4; i++)
                wmma::load_matrix_sync(af[i], as + (wm * 64 + i * 16) * ALD + ks * 16, ALD);
            #pragma unroll
            for (int j = 0; j < 4; j++) {
                wmma::fragment<wmma::matrix_b, 16, 16, 16, __half, wmma::row_major> bf;
                wmma::load_matrix_sync(bf, bs + ks * 16 * BLDN + wn * 64 + j * 16, BLDN);
                #pragma unroll
                for (int i = 0; i < 4; i++) wmma::mma_sync(acc[i][j], af[i], bf, acc[i][j]);
            }
        }
    }

    #pragma unroll
    for (int i = 0; i < 4; i++)
        #pragma unroll
        for (int j = 0; j < 4; j++) {
            int rg = m0 + wm * 64 + i * 16, cg = n0 + wn * 64 + j * 16;
            wmma::store_matrix_sync(C + (size_t)rg * ldc + cg, acc[i][j], ldc, wmma::mem_row_major);
        }
}

// ---------------- final combine ---------------------------------------------
__global__ void final_kernel(const float* __restrict__ normQ, const float* __restrict__ cross,
                             const float* __restrict__ selfa, const float* __restrict__ g1,
                             const float* __restrict__ g2, float* __restrict__ out) {
    int b = blockIdx.x / SQ, r = blockIdx.x % SQ;
    size_t ci = ((size_t)b * SQ + r) * 256 + threadIdx.x;
    size_t si = ((size_t)b * ROWP + r) * 256 + threadIdx.x;
    float4 q = ((const float4*)normQ)[ci];
    float4 c = ((const float4*)cross)[ci];
    float4 s = ((const float4*)selfa)[si];
    float4 a = ((const float4*)g1)[threadIdx.x];
    float4 bb = ((const float4*)g2)[threadIdx.x];
    float4 o;
    o.x = q.x + bb.x * (c.x + a.x * s.x);
    o.y = q.y + bb.y * (c.y + a.y * s.y);
    o.z = q.z + bb.z * (c.z + a.z * s.z);
    o.w = q.w + bb.w * (c.w + a.w * s.w);
    ((float4*)out)[ci] = o;
}

// ---------------- launch ------------------------------------------------------
extern "C" void kernel_launch(void* const* d_in, const int* in_sizes, int n_in,
                              void* d_out, int out_size) {
    const float* input_features = (const float*)d_in[0];
    const float* query_feature  = (const float*)d_in[1];
    const float* n1w = (const float*)d_in[2];
    const float* n1b = (const float*)d_in[3];
    const float* n2w = (const float*)d_in[4];
    const float* n2b = (const float*)d_in[5];
    const float* n3w = (const float*)d_in[6];
    const float* n3b = (const float*)d_in[7];
    const float* g1  = (const float*)d_in[8];
    const float* g2  = (const float*)d_in[9];
    const float* fc1w = (const float*)d_in[10];
    const float* fc1b = (const float*)d_in[11];
    const float* fc2w = (const float*)d_in[12];
    const float* fc2b = (const float*)d_in[13];

    __half *normX_h, *normQ_h, *normC_h, *P2;
    float *xf, *normQ, *part, *cross, *S2, *selfa;
    cudaGetSymbolAddress((void**)&normX_h, g_normX_h);
    cudaGetSymbolAddress((void**)&xf,      g_xf);
    cudaGetSymbolAddress((void**)&normQ,   g_normQ);
    cudaGetSymbolAddress((void**)&normQ_h, g_normQ_h);
    cudaGetSymbolAddress((void**)&part,    g_part);
    cudaGetSymbolAddress((void**)&cross,   g_cross);
    cudaGetSymbolAddress((void**)&normC_h, g_normC_h);
    cudaGetSymbolAddress((void**)&S2,      g_S2);
    cudaGetSymbolAddress((void**)&P2,      g_P2);
    cudaGetSymbolAddress((void**)&selfa,   g_self);

    cudaFuncSetAttribute((const void*)gemm_qk_fused, cudaFuncAttributeMaxDynamicSharedMemorySize, QK_SMEM);
    cudaFuncSetAttribute((const void*)gemm_qk, cudaFuncAttributeMaxDynamicSharedMemorySize, QK_SMEM);
    cudaFuncSetAttribute((const void*)gemm_pv, cudaFuncAttributeMaxDynamicSharedMemorySize, PV_SMEM);
    cudaFuncSetAttribute((const void*)softmax_kernel, cudaFuncAttributeMaxDynamicSharedMemorySize, SQP * 4);

    const float scale = 0.03125f;   // 1024^-0.5

    // 1) layernorms (normX also emits Xf = LN(X) @ fc1^T)
    ln_kernel<<<NB * SK, 256>>>(input_features, n1w, n1b, normX_h, nullptr, fc1w, xf);
    ln_kernel<<<NB * SQ, 256>>>(query_feature,  n2w, n2b, normQ_h, normQ, nullptr, nullptr);

    // 2) fused cross attention: QK + partial softmax stats (no S matrix)
    gemm_qk_fused<<<dim3(ROWP / 128, NT, NB), 256, QK_SMEM>>>(
        normQ_h, normX_h, xf, part, SQ, SK, scale,
        (size_t)SQ * D_EMB, (size_t)SK * D_EMB);

    // 3) reduce partials + MLP -> cross_attended
    cross_reduce_mlp<<<NB * SQ, 256>>>(part, fc1b, fc2w, fc2b, cross);

    // 4) LN(cross) + self attention
    ln_kernel<<<NB * SQ, 256>>>(cross, n3w, n3b, normC_h, nullptr, nullptr, nullptr);
    gemm_qk<<<dim3(ROWP / 128, SQP / 128, NB), 256, QK_SMEM>>>(
        normC_h, normC_h, S2, SQ, SQ, D_EMB, SQP,
        (size_t)SQ * D_EMB, (size_t)SQ * D_EMB, (size_t)ROWP * SQP, scale);
    softmax_kernel<<<NB * SQ, 256, SQP * 4>>>(S2, P2, SQ, SQP, SQ, ROWP);
    gemm_pv<<<dim3(ROWP / 128, D_EMB / 256, NB), 256, PV_SMEM>>>(
        P2, normC_h, selfa, SQ, SQP, SQ, D_EMB, D_EMB,
        (size_t)ROWP * SQP, (size_t)SQ * D_EMB, (size_t)ROWP * D_EMB);

    // 5) combine
    final_kernel<<<NB * SQ, 256>>>(normQ, cross, selfa, g1, g2, (float*)d_out);
}

// round 10
// speedup vs baseline: 1.0511x; 1.0511x over previous
#include <cuda_runtime.h>
#include <cuda_fp16.h>
#include <mma.h>
#include <math.h>
#include <stdint.h>

using namespace nvcuda;

#define D_EMB 1024
#define NB 8
#define SQ 577
#define SK 13271
#define SKP 13312      // SK padded to 128
#define ROWP 640       // SQ padded to 128
#define SQP 640        // self-attn K padded
#define LNEPS 1e-5f

// ---------------- scratch (__device__ globals) ------------------------------
__device__ __half g_normX_h[(size_t)NB * SK * D_EMB];   // LN(input) fp16
__device__ float  g_xf     [(size_t)NB * SK * 4];       // normX @ fc1^T
__device__ float  g_normQ  [(size_t)NB * SQ * D_EMB];   // LN(query) fp32
__device__ __half g_normQ_h[(size_t)NB * SQ * D_EMB];
__device__ float  g_S      [(size_t)NB * ROWP * SKP];   // cross scores fp32
__device__ float  g_cross  [(size_t)NB * SQ * D_EMB];   // MLP out, compact
__device__ __half g_normC_h[(size_t)NB * SQ * D_EMB];
__device__ float  g_S2     [(size_t)NB * ROWP * SQP];
__device__ __half g_P2     [(size_t)NB * ROWP * SQP];
__device__ float  g_self   [(size_t)NB * ROWP * D_EMB];

// ---------------- reductions -------------------------------------------------
template <int NW>
__device__ __forceinline__ float block_sum_t(float v, float* red) {
    #pragma unroll
    for (int o = 16; o > 0; o >>= 1) v += __shfl_xor_sync(0xffffffffu, v, o);
    int w = threadIdx.x >> 5;
    if ((threadIdx.x & 31) == 0) red[w] = v;
    __syncthreads();
    float s = 0.f;
    #pragma unroll
    for (int i = 0; i < NW; i++) s += red[i];
    __syncthreads();
    return s;
}
template <int NW>
__device__ __forceinline__ float block_max_t(float v, float* red) {
    #pragma unroll
    for (int o = 16; o > 0; o >>= 1) v = fmaxf(v, __shfl_xor_sync(0xffffffffu, v, o));
    int w = threadIdx.x >> 5;
    if ((threadIdx.x & 31) == 0) red[w] = v;
    __syncthreads();
    float s = -INFINITY;
    #pragma unroll
    for (int i = 0; i < NW; i++) s = fmaxf(s, red[i]);
    __syncthreads();
    return s;
}
__device__ __forceinline__ float block_sum(float v, float* red) { return block_sum_t<8>(v, red); }
__device__ __forceinline__ float block_max(float v, float* red) { return block_max_t<8>(v, red); }

// ---------------- layernorm -> fp16 (+ optional fp32, + optional Xf) --------
__global__ void ln_kernel(const float* __restrict__ in, const float* __restrict__ w,
                          const float* __restrict__ b, __half* __restrict__ out_h,
                          float* __restrict__ out_f,
                          const float* __restrict__ fc1, float* __restrict__ xf) {
    __shared__ float red[8];
    __shared__ float red4[4][8];
    size_t row = blockIdx.x;
    float4 v = ((const float4*)(in + row * D_EMB))[threadIdx.x];
    float mean = block_sum(v.x + v.y + v.z + v.w, red) * (1.f / D_EMB);
    float dx = v.x - mean, dy = v.y - mean, dz = v.z - mean, dw = v.w - mean;
    float var = block_sum(dx*dx + dy*dy + dz*dz + dw*dw, red) * (1.f / D_EMB);
    float inv = rsqrtf(var + LNEPS);
    float4 w4 = ((const float4*)w)[threadIdx.x];
    float4 b4 = ((const float4*)b)[threadIdx.x];
    float ox = dx * inv * w4.x + b4.x;
    float oy = dy * inv * w4.y + b4.y;
    float oz = dz * inv * w4.z + b4.z;
    float ow = dw * inv * w4.w + b4.w;
    __half2 h0 = __floats2half2_rn(ox, oy);
    __half2 h1 = __floats2half2_rn(oz, ow);
    uint2 packed = { *(uint32_t*)&h0, *(uint32_t*)&h1 };
    ((uint2*)(out_h + row * D_EMB))[threadIdx.x] = packed;
    if (out_f) {
        float4 o = { ox, oy, oz, ow };
        ((float4*)(out_f + row * D_EMB))[threadIdx.x] = o;
    }
    if (fc1) {
        #pragma unroll
        for (int h = 0; h < 4; h++) {
            float4 f = ((const float4*)(fc1 + (size_t)h * D_EMB))[threadIdx.x];
            float p = ox * f.x + oy * f.y + oz * f.z + ow * f.w;
            #pragma unroll
            for (int o = 16; o > 0; o >>= 1) p += __shfl_xor_sync(0xffffffffu, p, o);
            if ((threadIdx.x & 31) == 0) red4[h][threadIdx.x >> 5] = p;
        }
        __syncthreads();
        if (threadIdx.x < 4) {
            float s = 0.f;
            #pragma unroll
            for (int i = 0; i < 8; i++) s += red4[threadIdx.x][i];
            xf[row * 4 + threadIdx.x] = s;
        }
    }
}

// ---------------- fused softmax + MLP (cross path), 512 thr, float4 ---------
// Per row r: probs = softmax(S row); h = gelu(probs @ Xf + b1);
// cross row = h @ fc2^T + b2. Never materializes probs.
__global__ __launch_bounds__(512)
void softmax_mlp_kernel(const float* __restrict__ S, const float* __restrict__ xf,
                        const float* __restrict__ b1, const float* __restrict__ fc2,
                        const float* __restrict__ b2, float* __restrict__ cross) {
    extern __shared__ float buf[];
    __shared__ float red[16];
    __shared__ float hh[4];
    constexpr int T = 512;
    constexpr int N4 = SK >> 2;               // 3317 float4s
    int b = blockIdx.x / SQ, r = blockIdx.x % SQ;
    const float*  src  = S + ((size_t)b * ROWP + r) * SKP;
    const float4* src4 = (const float4*)src;
    const float4* xf4  = (const float4*)xf + (size_t)b * SK;
    float4* buf4 = (float4*)buf;

    float m = -INFINITY;
    for (int i = threadIdx.x; i < N4; i += T) {
        float4 v = src4[i];
        buf4[i] = v;
        m = fmaxf(fmaxf(fmaxf(m, v.x), fmaxf(v.y, v.z)), v.w);
    }
    for (int i = N4 * 4 + threadIdx.x; i < SK; i += T) {
        float v = src[i]; buf[i] = v; m = fmaxf(m, v);
    }
    m = block_max_t<16>(m, red);

    float s = 0.f, a0 = 0.f, a1 = 0.f, a2 = 0.f, a3 = 0.f;
    for (int i = threadIdx.x; i < N4; i += T) {
        float4 v = buf4[i];
        float e0 = __expf(v.x - m), e1 = __expf(v.y - m);
        float e2 = __expf(v.z - m), e3 = __expf(v.w - m);
        s += (e0 + e1) + (e2 + e3);
        float4 x0 = xf4[i * 4 + 0];
        float4 x1 = xf4[i * 4 + 1];
        float4 x2 = xf4[i * 4 + 2];
        float4 x3 = xf4[i * 4 + 3];
        a0 += e0 * x0.x + e1 * x1.x + e2 * x2.x + e3 * x3.x;
        a1 += e0 * x0.y + e1 * x1.y + e2 * x2.y + e3 * x3.y;
        a2 += e0 * x0.z + e1 * x1.z + e2 * x2.z + e3 * x3.z;
        a3 += e0 * x0.w + e1 * x1.w + e2 * x2.w + e3 * x3.w;
    }
    for (int i = N4 * 4 + threadIdx.x; i < SK; i += T) {
        float e = __expf(buf[i] - m);
        s += e;
        float4 x = xf4[i];
        a0 += e * x.x; a1 += e * x.y; a2 += e * x.z; a3 += e * x.w;
    }
    s  = block_sum_t<16>(s,  red);
    a0 = block_sum_t<16>(a0, red);
    a1 = block_sum_t<16>(a1, red);
    a2 = block_sum_t<16>(a2, red);
    a3 = block_sum_t<16>(a3, red);

    if (threadIdx.x == 0) {
        float inv = 1.f / s;
        const float k = 0.70710678118654752f;
        float p0 = a0 * inv + b1[0];
        float p1 = a1 * inv + b1[1];
        float p2 = a2 * inv + b1[2];
        float p3 = a3 * inv + b1[3];
        hh[0] = 0.5f * p0 * (1.f + erff(p0 * k));
        hh[1] = 0.5f * p1 * (1.f + erff(p1 * k));
        hh[2] = 0.5f * p2 * (1.f + erff(p2 * k));
        hh[3] = 0.5f * p3 * (1.f + erff(p3 * k));
    }
    __syncthreads();
    if (threadIdx.x < 256) {
        float h0 = hh[0], h1 = hh[1], h2 = hh[2], h3 = hh[3];
        int d = threadIdx.x * 4;
        float* dst = cross + ((size_t)b * SQ + r) * D_EMB + d;
        float4 o;
        { float4 wv = ((const float4*)fc2)[d + 0]; o.x = h0*wv.x + h1*wv.y + h2*wv.z + h3*wv.w + b2[d + 0]; }
        { float4 wv = ((const float4*)fc2)[d + 1]; o.y = h0*wv.x + h1*wv.y + h2*wv.z + h3*wv.w + b2[d + 1]; }
        { float4 wv = ((const float4*)fc2)[d + 2]; o.z = h0*wv.x + h1*wv.y + h2*wv.z + h3*wv.w + b2[d + 2]; }
        { float4 wv = ((const float4*)fc2)[d + 3]; o.w = h0*wv.x + h1*wv.y + h2*wv.z + h3*wv.w + b2[d + 3]; }
        *(float4*)dst = o;
    }
}

// ---------------- classic softmax (self path): fp32 in -> fp16 probs --------
__global__ void softmax_kernel(const float* __restrict__ S, __half* __restrict__ P,
                               int n, int np, int sq, int rowp) {
    extern __shared__ float buf[];
    __shared__ float red[8];
    int b = blockIdx.x / sq, r = blockIdx.x % sq;
    const float* src = S + ((size_t)b * rowp + r) * np;
    __half* dst = P + ((size_t)b * rowp + r) * np;
    float m = -INFINITY;
    for (int i = threadIdx.x; i < n; i += 256) { float v = src[i]; buf[i] = v; m = fmaxf(m, v); }
    m = block_max(m, red);
    float s = 0.f;
    for (int i = threadIdx.x; i < n; i += 256) { float e = __expf(buf[i] - m); buf[i] = e; s += e; }
    s = block_sum(s, red);
    float inv = 1.f / s;
    for (int i = threadIdx.x; i < n; i += 256) dst[i] = __float2half_rn(buf[i] * inv);
    for (int i = n + threadIdx.x; i < np; i += 256) dst[i] = __ushort_as_half(0);
}

// ---------------- cp.async helper -------------------------------------------
__device__ __forceinline__ void cp16(void* dst, const void* src, bool pred) {
    uint32_t d = (uint32_t)__cvta_generic_to_shared(dst);
    int sz = pred ? 16 : 0;
    asm volatile("cp.async.cg.shared.global [%0], [%1], 16, %2;\n" :: "r"(d), "l"(src), "r"(sz));
}

// ---------------- QK GEMM: NT fp16 wmma, 128x128x64, 3-stage ----------------
#define QK_SMEM (3 * (128 * 72 + 128 * 72) * 2)
__global__ __launch_bounds__(256)
void gemm_qk(const __half* __restrict__ A, const __half* __restrict__ B, float* __restrict__ C,
             int Mreal, int Nreal, int K, int ldc,
             size_t sA, size_t sB, size_t sC, float alpha) {
    constexpr int ALD = 72;
    constexpr int ASZ = 128 * ALD;
    constexpr int STAGE = 2 * ASZ;

    extern __shared__ __half smh[];

    A += blockIdx.z * sA;  B += blockIdx.z * sB;  C += blockIdx.z * sC;
    const int m0 = blockIdx.x * 128, n0 = blockIdx.y * 128;
    const int tid = threadIdx.x, warp = tid >> 5;
    const int wm = warp >> 1, wn = warp & 1;

    wmma::fragment<wmma::accumulator, 16, 16, 16, float> acc[2][4];
    #pragma unroll
    for (int i = 0; i < 2; i++)
        #pragma unroll
        for (int j = 0; j < 4; j++) wmma::fill_fragment(acc[i][j], 0.f);

    auto load_tile = [&](int kt, int bufi) {
        const int k0 = kt * 64;
        __half* as = smh + bufi * STAGE;
        __half* bs = as + ASZ;
        #pragma unroll
        for (int i = 0; i < 4; i++) {
            int idx = tid + i * 256;
            int r = idx >> 3, v = (idx & 7) * 8;
            int gr = m0 + r;
            cp16(as + r * ALD + v, A + (size_t)gr * K + k0 + v, gr < Mreal);
        }
        #pragma unroll
        for (int i = 0; i < 4; i++) {
            int idx = tid + i * 256;
            int r = idx >> 3, v = (idx & 7) * 8;
            int gn = n0 + r;
            cp16(bs + r * ALD + v, B + (size_t)gn * K + k0 + v, gn < Nreal);
        }
        asm volatile("cp.async.commit_group;\n");
    };

    const int KT = K / 64;
    load_tile(0, 0);
    if (KT > 1) load_tile(1, 1);

    for (int kt = 0; kt < KT; kt++) {
        if (kt + 1 < KT) asm volatile("cp.async.wait_group 1;\n");
        else             asm volatile("cp.async.wait_group 0;\n");
        __syncthreads();
        if (kt + 2 < KT) load_tile(kt + 2, (kt + 2) % 3);

        __half* as = smh + (kt % 3) * STAGE;
        __half* bs = as + ASZ;
        #pragma unroll
        for (int ks = 0; ks < 4; ks++) {
            wmma::fragment<wmma::matrix_a, 16, 16, 16, __half, wmma::row_major> af[2];
            #pragma unroll
            for (int i = 0; i < 2; i++)
                wmma::load_matrix_sync(af[i], as + (wm * 32 + i * 16) * ALD + ks * 16, ALD);
            #pragma unroll
            for (int j = 0; j < 4; j++) {
                wmma::fragment<wmma::matrix_b, 16, 16, 16, __half, wmma::col_major> bf;
                wmma::load_matrix_sync(bf, bs + (wn * 64 + j * 16) * ALD + ks * 16, ALD);
                #pragma unroll
                for (int i = 0; i < 2; i++) wmma::mma_sync(acc[i][j], af[i], bf, acc[i][j]);
            }
        }
    }

    #pragma unroll
    for (int i = 0; i < 2; i++)
        #pragma unroll
        for (int j = 0; j < 4; j++) {
            #pragma unroll
            for (int e = 0; e < 8; e++) acc[i][j].x[e] *= alpha;
            int rg = m0 + wm * 32 + i * 16, cg = n0 + wn * 64 + j * 16;
            wmma::store_matrix_sync(C + (size_t)rg * ldc + cg, acc[i][j], ldc, wmma::mem_row_major);
        }
}

// ---------------- PV GEMM (self path): NN fp16 wmma, 128x256x32, 4-stage ----
#define PV_SMEM (4 * (128 * 40 + 32 * 264) * 2)
__global__ __launch_bounds__(256)
void gemm_pv(const __half* __restrict__ A, const __half* __restrict__ B, float* __restrict__ C,
             int Mreal, int K, int Kreal, int ldb_n, int ldc,
             size_t sA, size_t sB, size_t sC) {
    constexpr int BN = 256;
    constexpr int ALD = 40;
    constexpr int ASZ = 128 * ALD;
    constexpr int BLDN = BN + 8;
    constexpr int BSZ = 32 * BLDN;
    constexpr int STAGE = ASZ + BSZ;
    constexpr int NS = 4;

    extern __shared__ __half smh[];

    A += blockIdx.z * sA;  B += blockIdx.z * sB;  C += blockIdx.z * sC;
    const int m0 = blockIdx.x * 128, n0 = blockIdx.y * BN;
    const int tid = threadIdx.x, warp = tid >> 5;
    const int wm = warp >> 2, wn = warp & 3;

    wmma::fragment<wmma::accumulator, 16, 16, 16, float> acc[4][4];
    #pragma unroll
    for (int i = 0; i < 4; i++)
        #pragma unroll
        for (int j = 0; j < 4; j++) wmma::fill_fragment(acc[i][j], 0.f);

    auto load_tile = [&](int kt, int bufi) {
        const int k0 = kt * 32;
        __half* as = smh + bufi * STAGE;
        __half* bs = as + ASZ;
        #pragma unroll
        for (int i = 0; i < 2; i++) {
            int idx = tid + i * 256;
            int r = idx >> 2, v = (idx & 3) * 8;
            int gr = m0 + r;
            cp16(as + r * ALD + v, A + (size_t)gr * K + k0 + v, gr < Mreal);
        }
        #pragma unroll
        for (int i = 0; i < 4; i++) {
            int idx = tid + i * 256;
            int kk = idx >> 5, v = (idx & 31) * 8;
            int gk = k0 + kk;
            cp16(bs + kk * BLDN + v, B + (size_t)gk * ldb_n + n0 + v, gk < Kreal);
        }
        asm volatile("cp.async.commit_group;\n");
    };

    const int KT = K / 32;
    load_tile(0, 0);
    load_tile(1, 1);
    load_tile(2, 2);

    for (int kt = 0; kt < KT; kt++) {
        const int pend = KT - kt - 1;
        if (pend >= 2)      asm volatile("cp.async.wait_group 2;\n");
        else if (pend == 1) asm volatile("cp.async.wait_group 1;\n");
        else                asm volatile("cp.async.wait_group 0;\n");
        __syncthreads();
        if (kt + 3 < KT) load_tile(kt + 3, (kt + 3) % NS);

        __half* as = smh + (kt % NS) * STAGE;
        __half* bs = as + ASZ;
        #pragma unroll
        for (int ks = 0; ks < 2; ks++) {
            wmma::fragment<wmma::matrix_a, 16, 16, 16, __half, wmma::row_major> af[4];
            #pragma unroll
            for (int i = 0; i < 4; i++)
                wmma::load_matrix_sync(af[i], as + (wm * 64 + i * 16) * ALD + ks * 16, ALD);
            #pragma unroll
            for (int j = 0; j < 4; j++) {
                wmma::fragment<wmma::matrix_b, 16, 16, 16, __half, wmma::row_major> bf;
                wmma::load_matrix_sync(bf, bs + ks * 16 * BLDN + wn * 64 + j * 16, BLDN);
                #pragma unroll
                for (int i = 0; i < 4; i++) wmma::mma_sync(acc[i][j], af[i], bf, acc[i][j]);
            }
        }
    }

    #pragma unroll
    for (int i = 0; i < 4; i++)
        #pragma unroll
        for (int j = 0; j < 4; j++) {
            int rg = m0 + wm * 64 + i * 16, cg = n0 + wn * 64 + j * 16;
            wmma::store_matrix_sync(C + (size_t)rg * ldc + cg, acc[i][j], ldc, wmma::mem_row_major);
        }
}

// ---------------- final combine ---------------------------------------------
__global__ void final_kernel(const float* __restrict__ normQ, const float* __restrict__ cross,
                             const float* __restrict__ selfa, const float* __restrict__ g1,
                             const float* __restrict__ g2, float* __restrict__ out) {
    int b = blockIdx.x / SQ, r = blockIdx.x % SQ;
    size_t ci = ((size_t)b * SQ + r) * 256 + threadIdx.x;
    size_t si = ((size_t)b * ROWP + r) * 256 + threadIdx.x;
    float4 q = ((const float4*)normQ)[ci];
    float4 c = ((const float4*)cross)[ci];
    float4 s = ((const float4*)selfa)[si];
    float4 a = ((const float4*)g1)[threadIdx.x];
    float4 bb = ((const float4*)g2)[threadIdx.x];
    float4 o;
    o.x = q.x + bb.x * (c.x + a.x * s.x);
    o.y = q.y + bb.y * (c.y + a.y * s.y);
    o.z = q.z + bb.z * (c.z + a.z * s.z);
    o.w = q.w + bb.w * (c.w + a.w * s.w);
    ((float4*)out)[ci] = o;
}

// ---------------- launch ------------------------------------------------------
extern "C" void kernel_launch(void* const* d_in, const int* in_sizes, int n_in,
                              void* d_out, int out_size) {
    const float* input_features = (const float*)d_in[0];
    const float* query_feature  = (const float*)d_in[1];
    const float* n1w = (const float*)d_in[2];
    const float* n1b = (const float*)d_in[3];
    const float* n2w = (const float*)d_in[4];
    const float* n2b = (const float*)d_in[5];
    const float* n3w = (const float*)d_in[6];
    const float* n3b = (const float*)d_in[7];
    const float* g1  = (const float*)d_in[8];
    const float* g2  = (const float*)d_in[9];
    const float* fc1w = (const float*)d_in[10];
    const float* fc1b = (const float*)d_in[11];
    const float* fc2w = (const float*)d_in[12];
    const float* fc2b = (const float*)d_in[13];

    __half *normX_h, *normQ_h, *normC_h, *P2;
    float *xf, *normQ, *S, *cross, *S2, *selfa;
    cudaGetSymbolAddress((void**)&normX_h, g_normX_h);
    cudaGetSymbolAddress((void**)&xf,      g_xf);
    cudaGetSymbolAddress((void**)&normQ,   g_normQ);
    cudaGetSymbolAddress((void**)&normQ_h, g_normQ_h);
    cudaGetSymbolAddress((void**)&S,       g_S);
    cudaGetSymbolAddress((void**)&cross,   g_cross);
    cudaGetSymbolAddress((void**)&normC_h, g_normC_h);
    cudaGetSymbolAddress((void**)&S2,      g_S2);
    cudaGetSymbolAddress((void**)&P2,      g_P2);
    cudaGetSymbolAddress((void**)&selfa,   g_self);

    cudaFuncSetAttribute((const void*)gemm_qk, cudaFuncAttributeMaxDynamicSharedMemorySize, QK_SMEM);
    cudaFuncSetAttribute((const void*)gemm_pv, cudaFuncAttributeMaxDynamicSharedMemorySize, PV_SMEM);
    cudaFuncSetAttribute((const void*)softmax_mlp_kernel, cudaFuncAttributeMaxDynamicSharedMemorySize, SKP * 4);
    cudaFuncSetAttribute((const void*)softmax_kernel, cudaFuncAttributeMaxDynamicSharedMemorySize, SQP * 4);

    const float scale = 0.03125f;   // 1024^-0.5

    // 1) layernorms (normX also emits Xf = LN(X) @ fc1^T, fused)
    ln_kernel<<<NB * SK, 256>>>(input_features, n1w, n1b, normX_h, nullptr, fc1w, xf);
    ln_kernel<<<NB * SQ, 256>>>(query_feature,  n2w, n2b, normQ_h, normQ, nullptr, nullptr);

    // 2) cross attention scores
    gemm_qk<<<dim3(ROWP / 128, SKP / 128, NB), 256, QK_SMEM>>>(
        normQ_h, normX_h, S, SQ, SK, D_EMB, SKP,
        (size_t)SQ * D_EMB, (size_t)SK * D_EMB, (size_t)ROWP * SKP, scale);

    // 3) fused softmax + MLP -> cross_attended (PV GEMM algebraically removed)
    softmax_mlp_kernel<<<NB * SQ, 512, SKP * 4>>>(S, xf, fc1b, fc2w, fc2b, cross);

    // 4) LN(cross) + self attention
    ln_kernel<<<NB * SQ, 256>>>(cross, n3w, n3b, normC_h, nullptr, nullptr, nullptr);
    gemm_qk<<<dim3(ROWP / 128, SQP / 128, NB), 256, QK_SMEM>>>(
        normC_h, normC_h, S2, SQ, SQ, D_EMB, SQP,
        (size_t)SQ * D_EMB, (size_t)SQ * D_EMB, (size_t)ROWP * SQP, scale);
    softmax_kernel<<<NB * SQ, 256, SQP * 4>>>(S2, P2, SQ, SQP, SQ, ROWP);
    gemm_pv<<<dim3(ROWP / 128, D_EMB / 256, NB), 256, PV_SMEM>>>(
        P2, normC_h, selfa, SQ, SQP, SQ, D_EMB, D_EMB,
        (size_t)ROWP * SQP, (size_t)SQ * D_EMB, (size_t)ROWP * D_EMB);

    // 5) combine
    final_kernel<<<NB * SQ, 256>>>(normQ, cross, selfa, g1, g2, (float*)d_out);
}

// round 11
// speedup vs baseline: 1.1274x; 1.0726x over previous
#include <cuda_runtime.h>
#include <cuda_fp16.h>
#include <mma.h>
#include <math.h>
#include <stdint.h>

using namespace nvcuda;

#define D_EMB 1024
#define NB 8
#define SQ 577
#define SK 13271
#define SKP 13312      // SK padded to 128
#define ROWP 640       // SQ padded to 128
#define SQP 640        // self-attn K padded
#define LNEPS 1e-5f

// ---------------- scratch (__device__ globals) ------------------------------
__device__ __half g_normX_h[(size_t)NB * SK * D_EMB];   // LN(input) fp16
__device__ float  g_xf     [(size_t)NB * SK * 4];       // normX @ fc1^T
__device__ float  g_normQ  [(size_t)NB * SQ * D_EMB];   // LN(query) fp32
__device__ __half g_normQ_h[(size_t)NB * SQ * D_EMB];
__device__ float  g_S      [(size_t)NB * ROWP * SKP];   // cross scores fp32
__device__ float  g_cross  [(size_t)NB * SQ * D_EMB];   // MLP out, compact
__device__ __half g_normC_h[(size_t)NB * SQ * D_EMB];
__device__ float  g_S2     [(size_t)NB * ROWP * SQP];
__device__ __half g_P2     [(size_t)NB * ROWP * SQP];
__device__ float  g_self   [(size_t)NB * ROWP * D_EMB];

// ---------------- reductions (blockDim == 256) ------------------------------
__device__ __forceinline__ float block_sum(float v, float* red) {
    #pragma unroll
    for (int o = 16; o > 0; o >>= 1) v += __shfl_xor_sync(0xffffffffu, v, o);
    int w = threadIdx.x >> 5;
    if ((threadIdx.x & 31) == 0) red[w] = v;
    __syncthreads();
    float s = 0.f;
    #pragma unroll
    for (int i = 0; i < 8; i++) s += red[i];
    __syncthreads();
    return s;
}
__device__ __forceinline__ float block_max(float v, float* red) {
    #pragma unroll
    for (int o = 16; o > 0; o >>= 1) v = fmaxf(v, __shfl_xor_sync(0xffffffffu, v, o));
    int w = threadIdx.x >> 5;
    if ((threadIdx.x & 31) == 0) red[w] = v;
    __syncthreads();
    float s = -INFINITY;
    #pragma unroll
    for (int i = 0; i < 8; i++) s = fmaxf(s, red[i]);
    __syncthreads();
    return s;
}

// ---------------- layernorm -> fp16 (+ optional fp32, + optional Xf) --------
__global__ void ln_kernel(const float* __restrict__ in, const float* __restrict__ w,
                          const float* __restrict__ b, __half* __restrict__ out_h,
                          float* __restrict__ out_f,
                          const float* __restrict__ fc1, float* __restrict__ xf) {
    __shared__ float red[8];
    __shared__ float red4[4][8];
    size_t row = blockIdx.x;
    float4 v = ((const float4*)(in + row * D_EMB))[threadIdx.x];
    float mean = block_sum(v.x + v.y + v.z + v.w, red) * (1.f / D_EMB);
    float dx = v.x - mean, dy = v.y - mean, dz = v.z - mean, dw = v.w - mean;
    float var = block_sum(dx*dx + dy*dy + dz*dz + dw*dw, red) * (1.f / D_EMB);
    float inv = rsqrtf(var + LNEPS);
    float4 w4 = ((const float4*)w)[threadIdx.x];
    float4 b4 = ((const float4*)b)[threadIdx.x];
    float ox = dx * inv * w4.x + b4.x;
    float oy = dy * inv * w4.y + b4.y;
    float oz = dz * inv * w4.z + b4.z;
    float ow = dw * inv * w4.w + b4.w;
    __half2 h0 = __floats2half2_rn(ox, oy);
    __half2 h1 = __floats2half2_rn(oz, ow);
    uint2 packed = { *(uint32_t*)&h0, *(uint32_t*)&h1 };
    ((uint2*)(out_h + row * D_EMB))[threadIdx.x] = packed;
    if (out_f) {
        float4 o = { ox, oy, oz, ow };
        ((float4*)(out_f + row * D_EMB))[threadIdx.x] = o;
    }
    if (fc1) {
        #pragma unroll
        for (int h = 0; h < 4; h++) {
            float4 f = ((const float4*)(fc1 + (size_t)h * D_EMB))[threadIdx.x];
            float p = ox * f.x + oy * f.y + oz * f.z + ow * f.w;
            #pragma unroll
            for (int o = 16; o > 0; o >>= 1) p += __shfl_xor_sync(0xffffffffu, p, o);
            if ((threadIdx.x & 31) == 0) red4[h][threadIdx.x >> 5] = p;
        }
        __syncthreads();
        if (threadIdx.x < 4) {
            float s = 0.f;
            #pragma unroll
            for (int i = 0; i < 8; i++) s += red4[threadIdx.x][i];
            xf[row * 4 + threadIdx.x] = s;
        }
    }
}

// ---------------- fused ONLINE softmax + MLP (cross path) -------------------
// Single pass over S, no smem staging. Per-thread running (m, s, a[4]) with
// rescale on max update; block combine rescales to the global max. Exact
// softmax semantics (different factorization only).
__global__ __launch_bounds__(256)
void softmax_mlp_kernel(const float* __restrict__ S, const float* __restrict__ xf,
                        const float* __restrict__ b1, const float* __restrict__ fc2,
                        const float* __restrict__ b2, float* __restrict__ cross) {
    __shared__ float red[8];
    __shared__ float hh[4];
    constexpr int T = 256;
    constexpr int N4 = SK >> 2;               // 3317 float4s (tail 3 scalars)
    int b = blockIdx.x / SQ, r = blockIdx.x % SQ;
    const float*  src  = S + ((size_t)b * ROWP + r) * SKP;
    const float4* src4 = (const float4*)src;
    const float4* xf4  = (const float4*)xf + (size_t)b * SK;

    float m = -INFINITY, s = 0.f, a0 = 0.f, a1 = 0.f, a2 = 0.f, a3 = 0.f;
    for (int i = threadIdx.x; i < N4; i += T) {
        float4 v = src4[i];
        float vm = fmaxf(fmaxf(v.x, v.y), fmaxf(v.z, v.w));
        if (vm > m) {                          // rare after warm-up
            float sc = __expf(m - vm);
            s *= sc; a0 *= sc; a1 *= sc; a2 *= sc; a3 *= sc;
            m = vm;
        }
        float e0 = __expf(v.x - m), e1 = __expf(v.y - m);
        float e2 = __expf(v.z - m), e3 = __expf(v.w - m);
        s += (e0 + e1) + (e2 + e3);
        float4 x0 = xf4[i * 4 + 0];
        float4 x1 = xf4[i * 4 + 1];
        float4 x2 = xf4[i * 4 + 2];
        float4 x3 = xf4[i * 4 + 3];
        a0 += e0 * x0.x + e1 * x1.x + e2 * x2.x + e3 * x3.x;
        a1 += e0 * x0.y + e1 * x1.y + e2 * x2.y + e3 * x3.y;
        a2 += e0 * x0.z + e1 * x1.z + e2 * x2.z + e3 * x3.z;
        a3 += e0 * x0.w + e1 * x1.w + e2 * x2.w + e3 * x3.w;
    }
    for (int i = N4 * 4 + threadIdx.x; i < SK; i += T) {
        float v = src[i];
        if (v > m) {
            float sc = __expf(m - v);
            s *= sc; a0 *= sc; a1 *= sc; a2 *= sc; a3 *= sc;
            m = v;
        }
        float e = __expf(v - m);
        s += e;
        float4 x = xf4[i];
        a0 += e * x.x; a1 += e * x.y; a2 += e * x.z; a3 += e * x.w;
    }

    // combine across threads: rescale partials to the global max, then sum
    float M = block_max(m, red);
    float sc = __expf(m - M);
    s *= sc; a0 *= sc; a1 *= sc; a2 *= sc; a3 *= sc;
    s  = block_sum(s,  red);
    a0 = block_sum(a0, red);
    a1 = block_sum(a1, red);
    a2 = block_sum(a2, red);
    a3 = block_sum(a3, red);

    if (threadIdx.x == 0) {
        float inv = 1.f / s;
        const float k = 0.70710678118654752f;
        float p0 = a0 * inv + b1[0];
        float p1 = a1 * inv + b1[1];
        float p2 = a2 * inv + b1[2];
        float p3 = a3 * inv + b1[3];
        hh[0] = 0.5f * p0 * (1.f + erff(p0 * k));
        hh[1] = 0.5f * p1 * (1.f + erff(p1 * k));
        hh[2] = 0.5f * p2 * (1.f + erff(p2 * k));
        hh[3] = 0.5f * p3 * (1.f + erff(p3 * k));
    }
    __syncthreads();
    float h0 = hh[0], h1 = hh[1], h2 = hh[2], h3 = hh[3];
    int d = threadIdx.x * 4;
    float* dst = cross + ((size_t)b * SQ + r) * D_EMB + d;
    float4 o;
    { float4 wv = ((const float4*)fc2)[d + 0]; o.x = h0*wv.x + h1*wv.y + h2*wv.z + h3*wv.w + b2[d + 0]; }
    { float4 wv = ((const float4*)fc2)[d + 1]; o.y = h0*wv.x + h1*wv.y + h2*wv.z + h3*wv.w + b2[d + 1]; }
    { float4 wv = ((const float4*)fc2)[d + 2]; o.z = h0*wv.x + h1*wv.y + h2*wv.z + h3*wv.w + b2[d + 2]; }
    { float4 wv = ((const float4*)fc2)[d + 3]; o.w = h0*wv.x + h1*wv.y + h2*wv.z + h3*wv.w + b2[d + 3]; }
    *(float4*)dst = o;
}

// ---------------- classic softmax (self path): fp32 in -> fp16 probs --------
__global__ void softmax_kernel(const float* __restrict__ S, __half* __restrict__ P,
                               int n, int np, int sq, int rowp) {
    extern __shared__ float buf[];
    __shared__ float red[8];
    int b = blockIdx.x / sq, r = blockIdx.x % sq;
    const float* src = S + ((size_t)b * rowp + r) * np;
    __half* dst = P + ((size_t)b * rowp + r) * np;
    float m = -INFINITY;
    for (int i = threadIdx.x; i < n; i += 256) { float v = src[i]; buf[i] = v; m = fmaxf(m, v); }
    m = block_max(m, red);
    float s = 0.f;
    for (int i = threadIdx.x; i < n; i += 256) { float e = __expf(buf[i] - m); buf[i] = e; s += e; }
    s = block_sum(s, red);
    float inv = 1.f / s;
    for (int i = threadIdx.x; i < n; i += 256) dst[i] = __float2half_rn(buf[i] * inv);
    for (int i = n + threadIdx.x; i < np; i += 256) dst[i] = __ushort_as_half(0);
}

// ---------------- cp.async helper -------------------------------------------
__device__ __forceinline__ void cp16(void* dst, const void* src, bool pred) {
    uint32_t d = (uint32_t)__cvta_generic_to_shared(dst);
    int sz = pred ? 16 : 0;
    asm volatile("cp.async.cg.shared.global [%0], [%1], 16, %2;\n" :: "r"(d), "l"(src), "r"(sz));
}

// ---------------- QK GEMM: NT fp16 wmma, 128x128x64, 3-stage ----------------
#define QK_SMEM (3 * (128 * 72 + 128 * 72) * 2)
__global__ __launch_bounds__(256)
void gemm_qk(const __half* __restrict__ A, const __half* __restrict__ B, float* __restrict__ C,
             int Mreal, int Nreal, int K, int ldc,
             size_t sA, size_t sB, size_t sC, float alpha) {
    constexpr int ALD = 72;
    constexpr int ASZ = 128 * ALD;
    constexpr int STAGE = 2 * ASZ;

    extern __shared__ __half smh[];

    A += blockIdx.z * sA;  B += blockIdx.z * sB;  C += blockIdx.z * sC;
    const int m0 = blockIdx.x * 128, n0 = blockIdx.y * 128;
    const int tid = threadIdx.x, warp = tid >> 5;
    const int wm = warp >> 1, wn = warp & 1;

    wmma::fragment<wmma::accumulator, 16, 16, 16, float> acc[2][4];
    #pragma unroll
    for (int i = 0; i < 2; i++)
        #pragma unroll
        for (int j = 0; j < 4; j++) wmma::fill_fragment(acc[i][j], 0.f);

    auto load_tile = [&](int kt, int bufi) {
        const int k0 = kt * 64;
        __half* as = smh + bufi * STAGE;
        __half* bs = as + ASZ;
        #pragma unroll
        for (int i = 0; i < 4; i++) {
            int idx = tid + i * 256;
            int r = idx >> 3, v = (idx & 7) * 8;
            int gr = m0 + r;
            cp16(as + r * ALD + v, A + (size_t)gr * K + k0 + v, gr < Mreal);
        }
        #pragma unroll
        for (int i = 0; i < 4; i++) {
            int idx = tid + i * 256;
            int r = idx >> 3, v = (idx & 7) * 8;
            int gn = n0 + r;
            cp16(bs + r * ALD + v, B + (size_t)gn * K + k0 + v, gn < Nreal);
        }
        asm volatile("cp.async.commit_group;\n");
    };

    const int KT = K / 64;
    load_tile(0, 0);
    if (KT > 1) load_tile(1, 1);

    for (int kt = 0; kt < KT; kt++) {
        if (kt + 1 < KT) asm volatile("cp.async.wait_group 1;\n");
        else             asm volatile("cp.async.wait_group 0;\n");
        __syncthreads();
        if (kt + 2 < KT) load_tile(kt + 2, (kt + 2) % 3);

        __half* as = smh + (kt % 3) * STAGE;
        __half* bs = as + ASZ;
        #pragma unroll
        for (int ks = 0; ks < 4; ks++) {
            wmma::fragment<wmma::matrix_a, 16, 16, 16, __half, wmma::row_major> af[2];
            #pragma unroll
            for (int i = 0; i < 2; i++)
                wmma::load_matrix_sync(af[i], as + (wm * 32 + i * 16) * ALD + ks * 16, ALD);
            #pragma unroll
            for (int j = 0; j < 4; j++) {
                wmma::fragment<wmma::matrix_b, 16, 16, 16, __half, wmma::col_major> bf;
                wmma::load_matrix_sync(bf, bs + (wn * 64 + j * 16) * ALD + ks * 16, ALD);
                #pragma unroll
                for (int i = 0; i < 2; i++) wmma::mma_sync(acc[i][j], af[i], bf, acc[i][j]);
            }
        }
    }

    #pragma unroll
    for (int i = 0; i < 2; i++)
        #pragma unroll
        for (int j = 0; j < 4; j++) {
            #pragma unroll
            for (int e = 0; e < 8; e++) acc[i][j].x[e] *= alpha;
            int rg = m0 + wm * 32 + i * 16, cg = n0 + wn * 64 + j * 16;
            wmma::store_matrix_sync(C + (size_t)rg * ldc + cg, acc[i][j], ldc, wmma::mem_row_major);
        }
}

// ---------------- PV GEMM (self path): NN fp16 wmma, 128x256x32, 4-stage ----
#define PV_SMEM (4 * (128 * 40 + 32 * 264) * 2)
__global__ __launch_bounds__(256)
void gemm_pv(const __half* __restrict__ A, const __half* __restrict__ B, float* __restrict__ C,
             int Mreal, int K, int Kreal, int ldb_n, int ldc,
             size_t sA, size_t sB, size_t sC) {
    constexpr int BN = 256;
    constexpr int ALD = 40;
    constexpr int ASZ = 128 * ALD;
    constexpr int BLDN = BN + 8;
    constexpr int BSZ = 32 * BLDN;
    constexpr int STAGE = ASZ + BSZ;
    constexpr int NS = 4;

    extern __shared__ __half smh[];

    A += blockIdx.z * sA;  B += blockIdx.z * sB;  C += blockIdx.z * sC;
    const int m0 = blockIdx.x * 128, n0 = blockIdx.y * BN;
    const int tid = threadIdx.x, warp = tid >> 5;
    const int wm = warp >> 2, wn = warp & 3;

    wmma::fragment<wmma::accumulator, 16, 16, 16, float> acc[4][4];
    #pragma unroll
    for (int i = 0; i < 4; i++)
        #pragma unroll
        for (int j = 0; j < 4; j++) wmma::fill_fragment(acc[i][j], 0.f);

    auto load_tile = [&](int kt, int bufi) {
        const int k0 = kt * 32;
        __half* as = smh + bufi * STAGE;
        __half* bs = as + ASZ;
        #pragma unroll
        for (int i = 0; i < 2; i++) {
            int idx = tid + i * 256;
            int r = idx >> 2, v = (idx & 3) * 8;
            int gr = m0 + r;
            cp16(as + r * ALD + v, A + (size_t)gr * K + k0 + v, gr < Mreal);
        }
        #pragma unroll
        for (int i = 0; i < 4; i++) {
            int idx = tid + i * 256;
            int kk = idx >> 5, v = (idx & 31) * 8;
            int gk = k0 + kk;
            cp16(bs + kk * BLDN + v, B + (size_t)gk * ldb_n + n0 + v, gk < Kreal);
        }
        asm volatile("cp.async.commit_group;\n");
    };

    const int KT = K / 32;
    load_tile(0, 0);
    load_tile(1, 1);
    load_tile(2, 2);

    for (int kt = 0; kt < KT; kt++) {
        const int pend = KT - kt - 1;
        if (pend >= 2)      asm volatile("cp.async.wait_group 2;\n");
        else if (pend == 1) asm volatile("cp.async.wait_group 1;\n");
        else                asm volatile("cp.async.wait_group 0;\n");
        __syncthreads();
        if (kt + 3 < KT) load_tile(kt + 3, (kt + 3) % NS);

        __half* as = smh + (kt % NS) * STAGE;
        __half* bs = as + ASZ;
        #pragma unroll
        for (int ks = 0; ks < 2; ks++) {
            wmma::fragment<wmma::matrix_a, 16, 16, 16, __half, wmma::row_major> af[4];
            #pragma unroll
            for (int i = 0; i < 4; i++)
                wmma::load_matrix_sync(af[i], as + (wm * 64 + i * 16) * ALD + ks * 16, ALD);
            #pragma unroll
            for (int j = 0; j < 4; j++) {
                wmma::fragment<wmma::matrix_b, 16, 16, 16, __half, wmma::row_major> bf;
                wmma::load_matrix_sync(bf, bs + ks * 16 * BLDN + wn * 64 + j * 16, BLDN);
                #pragma unroll
                for (int i = 0; i < 4; i++) wmma::mma_sync(acc[i][j], af[i], bf, acc[i][j]);
            }
        }
    }

    #pragma unroll
    for (int i = 0; i < 4; i++)
        #pragma unroll
        for (int j = 0; j < 4; j++) {
            int rg = m0 + wm * 64 + i * 16, cg = n0 + wn * 64 + j * 16;
            wmma::store_matrix_sync(C + (size_t)rg * ldc + cg, acc[i][j], ldc, wmma::mem_row_major);
        }
}

// ---------------- final combine ---------------------------------------------
__global__ void final_kernel(const float* __restrict__ normQ, const float* __restrict__ cross,
                             const float* __restrict__ selfa, const float* __restrict__ g1,
                             const float* __restrict__ g2, float* __restrict__ out) {
    int b = blockIdx.x / SQ, r = blockIdx.x % SQ;
    size_t ci = ((size_t)b * SQ + r) * 256 + threadIdx.x;
    size_t si = ((size_t)b * ROWP + r) * 256 + threadIdx.x;
    float4 q = ((const float4*)normQ)[ci];
    float4 c = ((const float4*)cross)[ci];
    float4 s = ((const float4*)selfa)[si];
    float4 a = ((const float4*)g1)[threadIdx.x];
    float4 bb = ((const float4*)g2)[threadIdx.x];
    float4 o;
    o.x = q.x + bb.x * (c.x + a.x * s.x);
    o.y = q.y + bb.y * (c.y + a.y * s.y);
    o.z = q.z + bb.z * (c.z + a.z * s.z);
    o.w = q.w + bb.w * (c.w + a.w * s.w);
    ((float4*)out)[ci] = o;
}

// ---------------- launch ------------------------------------------------------
extern "C" void kernel_launch(void* const* d_in, const int* in_sizes, int n_in,
                              void* d_out, int out_size) {
    const float* input_features = (const float*)d_in[0];
    const float* query_feature  = (const float*)d_in[1];
    const float* n1w = (const float*)d_in[2];
    const float* n1b = (const float*)d_in[3];
    const float* n2w = (const float*)d_in[4];
    const float* n2b = (const float*)d_in[5];
    const float* n3w = (const float*)d_in[6];
    const float* n3b = (const float*)d_in[7];
    const float* g1  = (const float*)d_in[8];
    const float* g2  = (const float*)d_in[9];
    const float* fc1w = (const float*)d_in[10];
    const float* fc1b = (const float*)d_in[11];
    const float* fc2w = (const float*)d_in[12];
    const float* fc2b = (const float*)d_in[13];

    __half *normX_h, *normQ_h, *normC_h, *P2;
    float *xf, *normQ, *S, *cross, *S2, *selfa;
    cudaGetSymbolAddress((void**)&normX_h, g_normX_h);
    cudaGetSymbolAddress((void**)&xf,      g_xf);
    cudaGetSymbolAddress((void**)&normQ,   g_normQ);
    cudaGetSymbolAddress((void**)&normQ_h, g_normQ_h);
    cudaGetSymbolAddress((void**)&S,       g_S);
    cudaGetSymbolAddress((void**)&cross,   g_cross);
    cudaGetSymbolAddress((void**)&normC_h, g_normC_h);
    cudaGetSymbolAddress((void**)&S2,      g_S2);
    cudaGetSymbolAddress((void**)&P2,      g_P2);
    cudaGetSymbolAddress((void**)&selfa,   g_self);

    cudaFuncSetAttribute((const void*)gemm_qk, cudaFuncAttributeMaxDynamicSharedMemorySize, QK_SMEM);
    cudaFuncSetAttribute((const void*)gemm_pv, cudaFuncAttributeMaxDynamicSharedMemorySize, PV_SMEM);
    cudaFuncSetAttribute((const void*)softmax_kernel, cudaFuncAttributeMaxDynamicSharedMemorySize, SQP * 4);

    const float scale = 0.03125f;   // 1024^-0.5

    // 1) layernorms (normX also emits Xf = LN(X) @ fc1^T, fused)
    ln_kernel<<<NB * SK, 256>>>(input_features, n1w, n1b, normX_h, nullptr, fc1w, xf);
    ln_kernel<<<NB * SQ, 256>>>(query_feature,  n2w, n2b, normQ_h, normQ, nullptr, nullptr);

    // 2) cross attention scores
    gemm_qk<<<dim3(ROWP / 128, SKP / 128, NB), 256, QK_SMEM>>>(
        normQ_h, normX_h, S, SQ, SK, D_EMB, SKP,
        (size_t)SQ * D_EMB, (size_t)SK * D_EMB, (size_t)ROWP * SKP, scale);

    // 3) fused ONLINE softmax + MLP -> cross_attended (single pass, no smem)
    softmax_mlp_kernel<<<NB * SQ, 256>>>(S, xf, fc1b, fc2w, fc2b, cross);

    // 4) LN(cross) + self attention
    ln_kernel<<<NB * SQ, 256>>>(cross, n3w, n3b, normC_h, nullptr, nullptr, nullptr);
    gemm_qk<<<dim3(ROWP / 128, SQP / 128, NB), 256, QK_SMEM>>>(
        normC_h, normC_h, S2, SQ, SQ, D_EMB, SQP,
        (size_t)SQ * D_EMB, (size_t)SQ * D_EMB, (size_t)ROWP * SQP, scale);
    softmax_kernel<<<NB * SQ, 256, SQP * 4>>>(S2, P2, SQ, SQP, SQ, ROWP);
    gemm_pv<<<dim3(ROWP / 128, D_EMB / 256, NB), 256, PV_SMEM>>>(
        P2, normC_h, selfa, SQ, SQP, SQ, D_EMB, D_EMB,
        (size_t)ROWP * SQP, (size_t)SQ * D_EMB, (size_t)ROWP * D_EMB);

    // 5) combine
    final_kernel<<<NB * SQ, 256>>>(normQ, cross, selfa, g1, g2, (float*)d_out);
}

// round 13
// speedup vs baseline: 1.1955x; 1.0604x over previous
#include <cuda_runtime.h>
#include <cuda_fp16.h>
#include <mma.h>
#include <math.h>
#include <stdint.h>

using namespace nvcuda;

#define D_EMB 1024
#define NB 8
#define SQ 577
#define SK 13271
#define SKP 13312      // SK padded to 128 (also xf plane batch stride, 16B aligned)
#define ROWP 640       // SQ padded to 128
#define SQP 640        // self-attn K padded
#define LNEPS 1e-5f
#define XFPLANE ((size_t)NB * SKP)   // per-h plane stride in floats

// ---------------- scratch (__device__ globals) ------------------------------
__device__ __half g_normX_h[(size_t)NB * SK * D_EMB];   // LN(input) fp16
__device__ float  g_xfp    [4 * XFPLANE];               // planar: [h][b][SKP]
__device__ float  g_normQ  [(size_t)NB * SQ * D_EMB];   // LN(query) fp32
__device__ __half g_normQ_h[(size_t)NB * SQ * D_EMB];
__device__ float  g_S      [(size_t)NB * ROWP * SKP];   // cross scores fp32
__device__ float  g_cross  [(size_t)NB * SQ * D_EMB];   // MLP out, compact
__device__ __half g_normC_h[(size_t)NB * SQ * D_EMB];
__device__ float  g_S2     [(size_t)NB * ROWP * SQP];
__device__ __half g_P2     [(size_t)NB * ROWP * SQP];
__device__ float  g_self   [(size_t)NB * ROWP * D_EMB];

// ---------------- reductions (blockDim == 256) ------------------------------
__device__ __forceinline__ float block_sum(float v, float* red) {
    #pragma unroll
    for (int o = 16; o > 0; o >>= 1) v += __shfl_xor_sync(0xffffffffu, v, o);
    int w = threadIdx.x >> 5;
    if ((threadIdx.x & 31) == 0) red[w] = v;
    __syncthreads();
    float s = 0.f;
    #pragma unroll
    for (int i = 0; i < 8; i++) s += red[i];
    __syncthreads();
    return s;
}
__device__ __forceinline__ float block_max(float v, float* red) {
    #pragma unroll
    for (int o = 16; o > 0; o >>= 1) v = fmaxf(v, __shfl_xor_sync(0xffffffffu, v, o));
    int w = threadIdx.x >> 5;
    if ((threadIdx.x & 31) == 0) red[w] = v;
    __syncthreads();
    float s = -INFINITY;
    #pragma unroll
    for (int i = 0; i < 8; i++) s = fmaxf(s, red[i]);
    __syncthreads();
    return s;
}

// ---------------- layernorm -> fp16 (+ optional fp32, + optional planar Xf) -
// When fc1 != nullptr: grid is NB*SK rows; writes xfp[h][b][lr] with the
// 16B-aligned padded batch stride SKP.
__global__ void ln_kernel(const float* __restrict__ in, const float* __restrict__ w,
                          const float* __restrict__ b, __half* __restrict__ out_h,
                          float* __restrict__ out_f,
                          const float* __restrict__ fc1, float* __restrict__ xfp) {
    __shared__ float red[8];
    __shared__ float red4[4][8];
    size_t row = blockIdx.x;
    float4 v = ((const float4*)(in + row * D_EMB))[threadIdx.x];
    float mean = block_sum(v.x + v.y + v.z + v.w, red) * (1.f / D_EMB);
    float dx = v.x - mean, dy = v.y - mean, dz = v.z - mean, dw = v.w - mean;
    float var = block_sum(dx*dx + dy*dy + dz*dz + dw*dw, red) * (1.f / D_EMB);
    float inv = rsqrtf(var + LNEPS);
    float4 w4 = ((const float4*)w)[threadIdx.x];
    float4 b4 = ((const float4*)b)[threadIdx.x];
    float ox = dx * inv * w4.x + b4.x;
    float oy = dy * inv * w4.y + b4.y;
    float oz = dz * inv * w4.z + b4.z;
    float ow = dw * inv * w4.w + b4.w;
    __half2 h0 = __floats2half2_rn(ox, oy);
    __half2 h1 = __floats2half2_rn(oz, ow);
    uint2 packed = { *(uint32_t*)&h0, *(uint32_t*)&h1 };
    ((uint2*)(out_h + row * D_EMB))[threadIdx.x] = packed;
    if (out_f) {
        float4 o = { ox, oy, oz, ow };
        ((float4*)(out_f + row * D_EMB))[threadIdx.x] = o;
    }
    if (fc1) {
        #pragma unroll
        for (int h = 0; h < 4; h++) {
            float4 f = ((const float4*)(fc1 + (size_t)h * D_EMB))[threadIdx.x];
            float p = ox * f.x + oy * f.y + oz * f.z + ow * f.w;
            #pragma unroll
            for (int o = 16; o > 0; o >>= 1) p += __shfl_xor_sync(0xffffffffu, p, o);
            if ((threadIdx.x & 31) == 0) red4[h][threadIdx.x >> 5] = p;
        }
        __syncthreads();
        if (threadIdx.x < 4) {
            float s = 0.f;
            #pragma unroll
            for (int i = 0; i < 8; i++) s += red4[threadIdx.x][i];
            int bb = (int)(row / SK), lr = (int)(row % SK);
            xfp[(size_t)threadIdx.x * XFPLANE + (size_t)bb * SKP + lr] = s;
        }
    }
}

// ---------------- fused ONLINE softmax + MLP (cross path, planar xf) --------
// Single pass over S, no smem staging, coalesced 16B-aligned planar xf loads.
__global__ __launch_bounds__(256)
void softmax_mlp_kernel(const float* __restrict__ S, const float* __restrict__ xfp,
                        const float* __restrict__ b1, const float* __restrict__ fc2,
                        const float* __restrict__ b2, float* __restrict__ cross) {
    __shared__ float red[8];
    __shared__ float hh[4];
    constexpr int T = 256;
    constexpr int N4 = SK >> 2;               // 3317 float4s (tail 3 scalars)
    int b = blockIdx.x / SQ, r = blockIdx.x % SQ;
    const float*  src  = S + ((size_t)b * ROWP + r) * SKP;
    const float4* src4 = (const float4*)src;
    const float*  x0p = xfp + 0 * XFPLANE + (size_t)b * SKP;   // 16B aligned
    const float*  x1p = xfp + 1 * XFPLANE + (size_t)b * SKP;
    const float*  x2p = xfp + 2 * XFPLANE + (size_t)b * SKP;
    const float*  x3p = xfp + 3 * XFPLANE + (size_t)b * SKP;

    float m = -INFINITY, s = 0.f, a0 = 0.f, a1 = 0.f, a2 = 0.f, a3 = 0.f;
    for (int i = threadIdx.x; i < N4; i += T) {
        float4 v = src4[i];
        float vm = fmaxf(fmaxf(v.x, v.y), fmaxf(v.z, v.w));
        if (vm > m) {                          // rare after warm-up
            float sc = __expf(m - vm);
            s *= sc; a0 *= sc; a1 *= sc; a2 *= sc; a3 *= sc;
            m = vm;
        }
        float e0 = __expf(v.x - m), e1 = __expf(v.y - m);
        float e2 = __expf(v.z - m), e3 = __expf(v.w - m);
        s += (e0 + e1) + (e2 + e3);
        float4 x0 = ((const float4*)x0p)[i];   // coalesced: 16B lane stride
        float4 x1 = ((const float4*)x1p)[i];
        float4 x2 = ((const float4*)x2p)[i];
        float4 x3 = ((const float4*)x3p)[i];
        a0 += e0 * x0.x + e1 * x0.y + e2 * x0.z + e3 * x0.w;
        a1 += e0 * x1.x + e1 * x1.y + e2 * x1.z + e3 * x1.w;
        a2 += e0 * x2.x + e1 * x2.y + e2 * x2.z + e3 * x2.w;
        a3 += e0 * x3.x + e1 * x3.y + e2 * x3.z + e3 * x3.w;
    }
    for (int i = N4 * 4 + threadIdx.x; i < SK; i += T) {
        float v = src[i];
        if (v > m) {
            float sc = __expf(m - v);
            s *= sc; a0 *= sc; a1 *= sc; a2 *= sc; a3 *= sc;
            m = v;
        }
        float e = __expf(v - m);
        s += e;
        a0 += e * x0p[i]; a1 += e * x1p[i]; a2 += e * x2p[i]; a3 += e * x3p[i];
    }

    float M = block_max(m, red);
    float sc = __expf(m - M);
    s *= sc; a0 *= sc; a1 *= sc; a2 *= sc; a3 *= sc;
    s  = block_sum(s,  red);
    a0 = block_sum(a0, red);
    a1 = block_sum(a1, red);
    a2 = block_sum(a2, red);
    a3 = block_sum(a3, red);

    if (threadIdx.x == 0) {
        float inv = 1.f / s;
        const float k = 0.70710678118654752f;
        float p0 = a0 * inv + b1[0];
        float p1 = a1 * inv + b1[1];
        float p2 = a2 * inv + b1[2];
        float p3 = a3 * inv + b1[3];
        hh[0] = 0.5f * p0 * (1.f + erff(p0 * k));
        hh[1] = 0.5f * p1 * (1.f + erff(p1 * k));
        hh[2] = 0.5f * p2 * (1.f + erff(p2 * k));
        hh[3] = 0.5f * p3 * (1.f + erff(p3 * k));
    }
    __syncthreads();
    float h0 = hh[0], h1 = hh[1], h2 = hh[2], h3 = hh[3];
    int d = threadIdx.x * 4;
    float* dst = cross + ((size_t)b * SQ + r) * D_EMB + d;
    float4 o;
    { float4 wv = ((const float4*)fc2)[d + 0]; o.x = h0*wv.x + h1*wv.y + h2*wv.z + h3*wv.w + b2[d + 0]; }
    { float4 wv = ((const float4*)fc2)[d + 1]; o.y = h0*wv.x + h1*wv.y + h2*wv.z + h3*wv.w + b2[d + 1]; }
    { float4 wv = ((const float4*)fc2)[d + 2]; o.z = h0*wv.x + h1*wv.y + h2*wv.z + h3*wv.w + b2[d + 2]; }
    { float4 wv = ((const float4*)fc2)[d + 3]; o.w = h0*wv.x + h1*wv.y + h2*wv.z + h3*wv.w + b2[d + 3]; }
    *(float4*)dst = o;
}

// ---------------- classic softmax (self path): fp32 in -> fp16 probs --------
__global__ void softmax_kernel(const float* __restrict__ S, __half* __restrict__ P,
                               int n, int np, int sq, int rowp) {
    extern __shared__ float buf[];
    __shared__ float red[8];
    int b = blockIdx.x / sq, r = blockIdx.x % sq;
    const float* src = S + ((size_t)b * rowp + r) * np;
    __half* dst = P + ((size_t)b * rowp + r) * np;
    float m = -INFINITY;
    for (int i = threadIdx.x; i < n; i += 256) { float v = src[i]; buf[i] = v; m = fmaxf(m, v); }
    m = block_max(m, red);
    float s = 0.f;
    for (int i = threadIdx.x; i < n; i += 256) { float e = __expf(buf[i] - m); buf[i] = e; s += e; }
    s = block_sum(s, red);
    float inv = 1.f / s;
    for (int i = threadIdx.x; i < n; i += 256) dst[i] = __float2half_rn(buf[i] * inv);
    for (int i = n + threadIdx.x; i < np; i += 256) dst[i] = __ushort_as_half(0);
}

// ---------------- cp.async helper -------------------------------------------
__device__ __forceinline__ void cp16(void* dst, const void* src, bool pred) {
    uint32_t d = (uint32_t)__cvta_generic_to_shared(dst);
    int sz = pred ? 16 : 0;
    asm volatile("cp.async.cg.shared.global [%0], [%1], 16, %2;\n" :: "r"(d), "l"(src), "r"(sz));
}

// ---------------- QK GEMM: NT fp16 wmma, 128x128x64, 3-stage ----------------
#define QK_SMEM (3 * (128 * 72 + 128 * 72) * 2)
__global__ __launch_bounds__(256)
void gemm_qk(const __half* __restrict__ A, const __half* __restrict__ B, float* __restrict__ C,
             int Mreal, int Nreal, int K, int ldc,
             size_t sA, size_t sB, size_t sC, float alpha) {
    constexpr int ALD = 72;
    constexpr int ASZ = 128 * ALD;
    constexpr int STAGE = 2 * ASZ;

    extern __shared__ __half smh[];

    A += blockIdx.z * sA;  B += blockIdx.z * sB;  C += blockIdx.z * sC;
    const int m0 = blockIdx.x * 128, n0 = blockIdx.y * 128;
    const int tid = threadIdx.x, warp = tid >> 5;
    const int wm = warp >> 1, wn = warp & 1;

    wmma::fragment<wmma::accumulator, 16, 16, 16, float> acc[2][4];
    #pragma unroll
    for (int i = 0; i < 2; i++)
        #pragma unroll
        for (int j = 0; j < 4; j++) wmma::fill_fragment(acc[i][j], 0.f);

    auto load_tile = [&](int kt, int bufi) {
        const int k0 = kt * 64;
        __half* as = smh + bufi * STAGE;
        __half* bs = as + ASZ;
        #pragma unroll
        for (int i = 0; i < 4; i++) {
            int idx = tid + i * 256;
            int r = idx >> 3, v = (idx & 7) * 8;
            int gr = m0 + r;
            cp16(as + r * ALD + v, A + (size_t)gr * K + k0 + v, gr < Mreal);
        }
        #pragma unroll
        for (int i = 0; i < 4; i++) {
            int idx = tid + i * 256;
            int r = idx >> 3, v = (idx & 7) * 8;
            int gn = n0 + r;
            cp16(bs + r * ALD + v, B + (size_t)gn * K + k0 + v, gn < Nreal);
        }
        asm volatile("cp.async.commit_group;\n");
    };

    const int KT = K / 64;
    load_tile(0, 0);
    if (KT > 1) load_tile(1, 1);

    for (int kt = 0; kt < KT; kt++) {
        if (kt + 1 < KT) asm volatile("cp.async.wait_group 1;\n");
        else             asm volatile("cp.async.wait_group 0;\n");
        __syncthreads();
        if (kt + 2 < KT) load_tile(kt + 2, (kt + 2) % 3);

        __half* as = smh + (kt % 3) * STAGE;
        __half* bs = as + ASZ;
        #pragma unroll
        for (int ks = 0; ks < 4; ks++) {
            wmma::fragment<wmma::matrix_a, 16, 16, 16, __half, wmma::row_major> af[2];
            #pragma unroll
            for (int i = 0; i < 2; i++)
                wmma::load_matrix_sync(af[i], as + (wm * 32 + i * 16) * ALD + ks * 16, ALD);
            #pragma unroll
            for (int j = 0; j < 4; j++) {
                wmma::fragment<wmma::matrix_b, 16, 16, 16, __half, wmma::col_major> bf;
                wmma::load_matrix_sync(bf, bs + (wn * 64 + j * 16) * ALD + ks * 16, ALD);
                #pragma unroll
                for (int i = 0; i < 2; i++) wmma::mma_sync(acc[i][j], af[i], bf, acc[i][j]);
            }
        }
    }

    #pragma unroll
    for (int i = 0; i < 2; i++)
        #pragma unroll
        for (int j = 0; j < 4; j++) {
            #pragma unroll
            for (int e = 0; e < 8; e++) acc[i][j].x[e] *= alpha;
            int rg = m0 + wm * 32 + i * 16, cg = n0 + wn * 64 + j * 16;
            wmma::store_matrix_sync(C + (size_t)rg * ldc + cg, acc[i][j], ldc, wmma::mem_row_major);
        }
}

// ---------------- PV GEMM (self path): NN fp16 wmma, 128x256x32, 4-stage ----
#define PV_SMEM (4 * (128 * 40 + 32 * 264) * 2)
__global__ __launch_bounds__(256)
void gemm_pv(const __half* __restrict__ A, const __half* __restrict__ B, float* __restrict__ C,
             int Mreal, int K, int Kreal, int ldb_n, int ldc,
             size_t sA, size_t sB, size_t sC) {
    constexpr int BN = 256;
    constexpr int ALD = 40;
    constexpr int ASZ = 128 * ALD;
    constexpr int BLDN = BN + 8;
    constexpr int BSZ = 32 * BLDN;
    constexpr int STAGE = ASZ + BSZ;
    constexpr int NS = 4;

    extern __shared__ __half smh[];

    A += blockIdx.z * sA;  B += blockIdx.z * sB;  C += blockIdx.z * sC;
    const int m0 = blockIdx.x * 128, n0 = blockIdx.y * BN;
    const int tid = threadIdx.x, warp = tid >> 5;
    const int wm = warp >> 2, wn = warp & 3;

    wmma::fragment<wmma::accumulator, 16, 16, 16, float> acc[4][4];
    #pragma unroll
    for (int i = 0; i < 4; i++)
        #pragma unroll
        for (int j = 0; j < 4; j++) wmma::fill_fragment(acc[i][j], 0.f);

    auto load_tile = [&](int kt, int bufi) {
        const int k0 = kt * 32;
        __half* as = smh + bufi * STAGE;
        __half* bs = as + ASZ;
        #pragma unroll
        for (int i = 0; i < 2; i++) {
            int idx = tid + i * 256;
            int r = idx >> 2, v = (idx & 3) * 8;
            int gr = m0 + r;
            cp16(as + r * ALD + v, A + (size_t)gr * K + k0 + v, gr < Mreal);
        }
        #pragma unroll
        for (int i = 0; i < 4; i++) {
            int idx = tid + i * 256;
            int kk = idx >> 5, v = (idx & 31) * 8;
            int gk = k0 + kk;
            cp16(bs + kk * BLDN + v, B + (size_t)gk * ldb_n + n0 + v, gk < Kreal);
        }
        asm volatile("cp.async.commit_group;\n");
    };

    const int KT = K / 32;
    load_tile(0, 0);
    load_tile(1, 1);
    load_tile(2, 2);

    for (int kt = 0; kt < KT; kt++) {
        const int pend = KT - kt - 1;
        if (pend >= 2)      asm volatile("cp.async.wait_group 2;\n");
        else if (pend == 1) asm volatile("cp.async.wait_group 1;\n");
        else                asm volatile("cp.async.wait_group 0;\n");
        __syncthreads();
        if (kt + 3 < KT) load_tile(kt + 3, (kt + 3) % NS);

        __half* as = smh + (kt % NS) * STAGE;
        __half* bs = as + ASZ;
        #pragma unroll
        for (int ks = 0; ks < 2; ks++) {
            wmma::fragment<wmma::matrix_a, 16, 16, 16, __half, wmma::row_major> af[4];
            #pragma unroll
            for (int i = 0; i < 4; i++)
                wmma::load_matrix_sync(af[i], as + (wm * 64 + i * 16) * ALD + ks * 16, ALD);
            #pragma unroll
            for (int j = 0; j < 4; j++) {
                wmma::fragment<wmma::matrix_b, 16, 16, 16, __half, wmma::row_major> bf;
                wmma::load_matrix_sync(bf, bs + ks * 16 * BLDN + wn * 64 + j * 16, BLDN);
                #pragma unroll
                for (int i = 0; i < 4; i++) wmma::mma_sync(acc[i][j], af[i], bf, acc[i][j]);
            }
        }
    }

    #pragma unroll
    for (int i = 0; i < 4; i++)
        #pragma unroll
        for (int j = 0; j < 4; j++) {
            int rg = m0 + wm * 64 + i * 16, cg = n0 + wn * 64 + j * 16;
            wmma::store_matrix_sync(C + (size_t)rg * ldc + cg, acc[i][j], ldc, wmma::mem_row_major);
        }
}

// ---------------- final combine ---------------------------------------------
__global__ void final_kernel(const float* __restrict__ normQ, const float* __restrict__ cross,
                             const float* __restrict__ selfa, const float* __restrict__ g1,
                             const float* __restrict__ g2, float* __restrict__ out) {
    int b = blockIdx.x / SQ, r = blockIdx.x % SQ;
    size_t ci = ((size_t)b * SQ + r) * 256 + threadIdx.x;
    size_t si = ((size_t)b * ROWP + r) * 256 + threadIdx.x;
    float4 q = ((const float4*)normQ)[ci];
    float4 c = ((const float4*)cross)[ci];
    float4 s = ((const float4*)selfa)[si];
    float4 a = ((const float4*)g1)[threadIdx.x];
    float4 bb = ((const float4*)g2)[threadIdx.x];
    float4 o;
    o.x = q.x + bb.x * (c.x + a.x * s.x);
    o.y = q.y + bb.y * (c.y + a.y * s.y);
    o.z = q.z + bb.z * (c.z + a.z * s.z);
    o.w = q.w + bb.w * (c.w + a.w * s.w);
    ((float4*)out)[ci] = o;
}

// ---------------- launch ------------------------------------------------------
extern "C" void kernel_launch(void* const* d_in, const int* in_sizes, int n_in,
                              void* d_out, int out_size) {
    const float* input_features = (const float*)d_in[0];
    const float* query_feature  = (const float*)d_in[1];
    const float* n1w = (const float*)d_in[2];
    const float* n1b = (const float*)d_in[3];
    const float* n2w = (const float*)d_in[4];
    const float* n2b = (const float*)d_in[5];
    const float* n3w = (const float*)d_in[6];
    const float* n3b = (const float*)d_in[7];
    const float* g1  = (const float*)d_in[8];
    const float* g2  = (const float*)d_in[9];
    const float* fc1w = (const float*)d_in[10];
    const float* fc1b = (const float*)d_in[11];
    const float* fc2w = (const float*)d_in[12];
    const float* fc2b = (const float*)d_in[13];

    __half *normX_h, *normQ_h, *normC_h, *P2;
    float *xfp, *normQ, *S, *cross, *S2, *selfa;
    cudaGetSymbolAddress((void**)&normX_h, g_normX_h);
    cudaGetSymbolAddress((void**)&xfp,     g_xfp);
    cudaGetSymbolAddress((void**)&normQ,   g_normQ);
    cudaGetSymbolAddress((void**)&normQ_h, g_normQ_h);
    cudaGetSymbolAddress((void**)&S,       g_S);
    cudaGetSymbolAddress((void**)&cross,   g_cross);
    cudaGetSymbolAddress((void**)&normC_h, g_normC_h);
    cudaGetSymbolAddress((void**)&S2,      g_S2);
    cudaGetSymbolAddress((void**)&P2,      g_P2);
    cudaGetSymbolAddress((void**)&selfa,   g_self);

    cudaFuncSetAttribute((const void*)gemm_qk, cudaFuncAttributeMaxDynamicSharedMemorySize, QK_SMEM);
    cudaFuncSetAttribute((const void*)gemm_pv, cudaFuncAttributeMaxDynamicSharedMemorySize, PV_SMEM);
    cudaFuncSetAttribute((const void*)softmax_kernel, cudaFuncAttributeMaxDynamicSharedMemorySize, SQP * 4);

    const float scale = 0.03125f;   // 1024^-0.5

    // 1) layernorms (normX also emits planar Xf = LN(X) @ fc1^T)
    ln_kernel<<<NB * SK, 256>>>(input_features, n1w, n1b, normX_h, nullptr, fc1w, xfp);
    ln_kernel<<<NB * SQ, 256>>>(query_feature,  n2w, n2b, normQ_h, normQ, nullptr, nullptr);

    // 2) cross attention scores
    gemm_qk<<<dim3(ROWP / 128, SKP / 128, NB), 256, QK_SMEM>>>(
        normQ_h, normX_h, S, SQ, SK, D_EMB, SKP,
        (size_t)SQ * D_EMB, (size_t)SK * D_EMB, (size_t)ROWP * SKP, scale);

    // 3) fused ONLINE softmax + MLP -> cross_attended
    softmax_mlp_kernel<<<NB * SQ, 256>>>(S, xfp, fc1b, fc2w, fc2b, cross);

    // 4) LN(cross) + self attention
    ln_kernel<<<NB * SQ, 256>>>(cross, n3w, n3b, normC_h, nullptr, nullptr, nullptr);
    gemm_qk<<<dim3(ROWP / 128, SQP / 128, NB), 256, QK_SMEM>>>(
        normC_h, normC_h, S2, SQ, SQ, D_EMB, SQP,
        (size_t)SQ * D_EMB, (size_t)SQ * D_EMB, (size_t)ROWP * SQP, scale);
    softmax_kernel<<<NB * SQ, 256, SQP * 4>>>(S2, P2, SQ, SQP, SQ, ROWP);
    gemm_pv<<<dim3(ROWP / 128, D_EMB / 256, NB), 256, PV_SMEM>>>(
        P2, normC_h, selfa, SQ, SQP, SQ, D_EMB, D_EMB,
        (size_t)ROWP * SQP, (size_t)SQ * D_EMB, (size_t)ROWP * D_EMB);

    // 5) combine
    final_kernel<<<NB * SQ, 256>>>(normQ, cross, selfa, g1, g2, (float*)d_out);
}

// round 16
// speedup vs baseline: 1.2095x; 1.0118x over previous
#include <cuda_runtime.h>
#include <cuda_fp16.h>
#include <mma.h>
#include <math.h>
#include <stdint.h>

using namespace nvcuda;

#define D_EMB 1024
#define NB 8
#define SQ 577
#define SK 13271
#define SKP 13312      // SK padded to 128 (also xf batch stride, 16B aligned)
#define ROWP 640       // SQ padded to 128
#define SQP 640        // self-attn K padded
#define LNEPS 1e-5f
#define XFPLANE ((size_t)NB * SKP)   // per-h plane stride in floats
#define RPB 4                        // rows per softmax_mlp block
#define RBLK ((SQ + RPB - 1) / RPB)  // 145 row-groups per batch

// ---------------- scratch (__device__ globals) ------------------------------
__device__ __half g_normX_h[(size_t)NB * SK * D_EMB];   // LN(input) fp16
__device__ float  g_xfp    [4 * XFPLANE];               // planar: [h][b][SKP]
__device__ float  g_normQ  [(size_t)NB * SQ * D_EMB];   // LN(query) fp32
__device__ __half g_normQ_h[(size_t)NB * SQ * D_EMB];
__device__ float  g_S      [(size_t)NB * ROWP * SKP];   // cross scores fp32
__device__ float  g_cross  [(size_t)NB * SQ * D_EMB];   // MLP out, compact
__device__ __half g_normC_h[(size_t)NB * SQ * D_EMB];
__device__ float  g_S2     [(size_t)NB * ROWP * SQP];
__device__ __half g_P2     [(size_t)NB * ROWP * SQP];
__device__ float  g_self   [(size_t)NB * ROWP * D_EMB];

// ---------------- reductions (blockDim == 256) ------------------------------
__device__ __forceinline__ float block_sum(float v, float* red) {
    #pragma unroll
    for (int o = 16; o > 0; o >>= 1) v += __shfl_xor_sync(0xffffffffu, v, o);
    int w = threadIdx.x >> 5;
    if ((threadIdx.x & 31) == 0) red[w] = v;
    __syncthreads();
    float s = 0.f;
    #pragma unroll
    for (int i = 0; i < 8; i++) s += red[i];
    __syncthreads();
    return s;
}
__device__ __forceinline__ float block_max(float v, float* red) {
    #pragma unroll
    for (int o = 16; o > 0; o >>= 1) v = fmaxf(v, __shfl_xor_sync(0xffffffffu, v, o));
    int w = threadIdx.x >> 5;
    if ((threadIdx.x & 31) == 0) red[w] = v;
    __syncthreads();
    float s = -INFINITY;
    #pragma unroll
    for (int i = 0; i < 8; i++) s = fmaxf(s, red[i]);
    __syncthreads();
    return s;
}

// ---------------- layernorm -> fp16 (+ optional fp32, + optional planar Xf) -
__global__ void ln_kernel(const float* __restrict__ in, const float* __restrict__ w,
                          const float* __restrict__ b, __half* __restrict__ out_h,
                          float* __restrict__ out_f,
                          const float* __restrict__ fc1, float* __restrict__ xfp) {
    __shared__ float red[8];
    __shared__ float red4[4][8];
    size_t row = blockIdx.x;
    float4 v = ((const float4*)(in + row * D_EMB))[threadIdx.x];
    float mean = block_sum(v.x + v.y + v.z + v.w, red) * (1.f / D_EMB);
    float dx = v.x - mean, dy = v.y - mean, dz = v.z - mean, dw = v.w - mean;
    float var = block_sum(dx*dx + dy*dy + dz*dz + dw*dw, red) * (1.f / D_EMB);
    float inv = rsqrtf(var + LNEPS);
    float4 w4 = ((const float4*)w)[threadIdx.x];
    float4 b4 = ((const float4*)b)[threadIdx.x];
    float ox = dx * inv * w4.x + b4.x;
    float oy = dy * inv * w4.y + b4.y;
    float oz = dz * inv * w4.z + b4.z;
    float ow = dw * inv * w4.w + b4.w;
    __half2 h0 = __floats2half2_rn(ox, oy);
    __half2 h1 = __floats2half2_rn(oz, ow);
    uint2 packed = { *(uint32_t*)&h0, *(uint32_t*)&h1 };
    ((uint2*)(out_h + row * D_EMB))[threadIdx.x] = packed;
    if (out_f) {
        float4 o = { ox, oy, oz, ow };
        ((float4*)(out_f + row * D_EMB))[threadIdx.x] = o;
    }
    if (fc1) {
        #pragma unroll
        for (int h = 0; h < 4; h++) {
            float4 f = ((const float4*)(fc1 + (size_t)h * D_EMB))[threadIdx.x];
            float p = ox * f.x + oy * f.y + oz * f.z + ow * f.w;
            #pragma unroll
            for (int o = 16; o > 0; o >>= 1) p += __shfl_xor_sync(0xffffffffu, p, o);
            if ((threadIdx.x & 31) == 0) red4[h][threadIdx.x >> 5] = p;
        }
        __syncthreads();
        if (threadIdx.x < 4) {
            float s = 0.f;
            #pragma unroll
            for (int i = 0; i < 8; i++) s += red4[threadIdx.x][i];
            int bb = (int)(row / SK), lr = (int)(row % SK);
            xfp[(size_t)threadIdx.x * XFPLANE + (size_t)bb * SKP + lr] = s;
        }
    }
}

// ---------------- fused ONLINE softmax + MLP, 4 rows/block ------------------
// Each block processes RPB=4 rows of one batch; xf chunks are loaded once and
// applied to all 4 rows (4x less L2 traffic). Exact softmax semantics.
// FIX vs R15: thread-local max preserved (mloc) — rescale uses exp(mloc - M).
__global__ __launch_bounds__(256)
void softmax_mlp_kernel(const float* __restrict__ S, const float* __restrict__ xfp,
                        const float* __restrict__ b1, const float* __restrict__ fc2,
                        const float* __restrict__ b2, float* __restrict__ cross) {
    __shared__ float wred[8][24];
    __shared__ float Msh[RPB];
    __shared__ float Ssh[RPB * 5];
    __shared__ float hh[RPB][4];
    constexpr int T = 256;
    constexpr int N4 = SK >> 2;               // 3317 float4s (tail 3 scalars)
    const int b = blockIdx.x / RBLK, rb = blockIdx.x % RBLK;
    const int row0 = rb * RPB;
    const int wid = threadIdx.x >> 5, lane = threadIdx.x & 31;

    const float* x0p = xfp + 0 * XFPLANE + (size_t)b * SKP;
    const float* x1p = xfp + 1 * XFPLANE + (size_t)b * SKP;
    const float* x2p = xfp + 2 * XFPLANE + (size_t)b * SKP;
    const float* x3p = xfp + 3 * XFPLANE + (size_t)b * SKP;

    const float4* src4[RPB];
    const float*  srcs[RPB];
    bool act[RPB];
    #pragma unroll
    for (int r = 0; r < RPB; r++) {
        int row = row0 + r;
        act[r] = row < SQ;
        const float* p = S + ((size_t)b * ROWP + (act[r] ? row : row0)) * SKP;
        srcs[r] = p;
        src4[r] = (const float4*)p;
    }

    float m[RPB], s[RPB], a[RPB][4];
    #pragma unroll
    for (int r = 0; r < RPB; r++) {
        m[r] = -INFINITY; s[r] = 0.f;
        #pragma unroll
        for (int h = 0; h < 4; h++) a[r][h] = 0.f;
    }

    for (int i = threadIdx.x; i < N4; i += T) {
        float4 x0 = ((const float4*)x0p)[i];
        float4 x1 = ((const float4*)x1p)[i];
        float4 x2 = ((const float4*)x2p)[i];
        float4 x3 = ((const float4*)x3p)[i];
        #pragma unroll
        for (int r = 0; r < RPB; r++) {
            float4 v = src4[r][i];
            float vm = fmaxf(fmaxf(v.x, v.y), fmaxf(v.z, v.w));
            if (vm > m[r]) {                  // rare after warm-up
                float sc = __expf(m[r] - vm);
                s[r] *= sc; a[r][0] *= sc; a[r][1] *= sc; a[r][2] *= sc; a[r][3] *= sc;
                m[r] = vm;
            }
            float e0 = __expf(v.x - m[r]), e1 = __expf(v.y - m[r]);
            float e2 = __expf(v.z - m[r]), e3 = __expf(v.w - m[r]);
            s[r] += (e0 + e1) + (e2 + e3);
            a[r][0] += e0 * x0.x + e1 * x0.y + e2 * x0.z + e3 * x0.w;
            a[r][1] += e0 * x1.x + e1 * x1.y + e2 * x1.z + e3 * x1.w;
            a[r][2] += e0 * x2.x + e1 * x2.y + e2 * x2.z + e3 * x2.w;
            a[r][3] += e0 * x3.x + e1 * x3.y + e2 * x3.z + e3 * x3.w;
        }
    }
    for (int i = N4 * 4 + threadIdx.x; i < SK; i += T) {
        float xv0 = x0p[i], xv1 = x1p[i], xv2 = x2p[i], xv3 = x3p[i];
        #pragma unroll
        for (int r = 0; r < RPB; r++) {
            float v = srcs[r][i];
            if (v > m[r]) {
                float sc = __expf(m[r] - v);
                s[r] *= sc; a[r][0] *= sc; a[r][1] *= sc; a[r][2] *= sc; a[r][3] *= sc;
                m[r] = v;
            }
            float e = __expf(v - m[r]);
            s[r] += e;
            a[r][0] += e * xv0; a[r][1] += e * xv1; a[r][2] += e * xv2; a[r][3] += e * xv3;
        }
    }

    // ---- combine: warp shuffles + smem; thread-local max kept intact ----
    float mw[RPB];
    #pragma unroll
    for (int r = 0; r < RPB; r++) {
        float t = m[r];                       // warp max in t; m[r] stays thread-local
        #pragma unroll
        for (int o = 16; o > 0; o >>= 1) t = fmaxf(t, __shfl_xor_sync(0xffffffffu, t, o));
        mw[r] = t;
        if (lane == 0) wred[wid][r] = t;
    }
    __syncthreads();
    if (threadIdx.x < RPB) {
        float M = -INFINITY;
        #pragma unroll
        for (int w = 0; w < 8; w++) M = fmaxf(M, wred[w][threadIdx.x]);
        Msh[threadIdx.x] = M;
    }
    __syncthreads();
    #pragma unroll
    for (int r = 0; r < RPB; r++) {
        float sc = __expf(m[r] - Msh[r]);     // rescale by THREAD-LOCAL max delta
        s[r] *= sc; a[r][0] *= sc; a[r][1] *= sc; a[r][2] *= sc; a[r][3] *= sc;
        float vals[5] = { s[r], a[r][0], a[r][1], a[r][2], a[r][3] };
        #pragma unroll
        for (int j = 0; j < 5; j++) {
            float v = vals[j];
            #pragma unroll
            for (int o = 16; o > 0; o >>= 1) v += __shfl_xor_sync(0xffffffffu, v, o);
            if (lane == 0) wred[wid][r * 5 + j] = v;
        }
    }
    (void)mw;
    __syncthreads();
    if (threadIdx.x < RPB * 5) {
        float t = 0.f;
        #pragma unroll
        for (int w = 0; w < 8; w++) t += wred[w][threadIdx.x];
        Ssh[threadIdx.x] = t;
    }
    __syncthreads();
    if (threadIdx.x < RPB) {
        int r = threadIdx.x;
        float inv = 1.f / Ssh[r * 5 + 0];
        const float k = 0.70710678118654752f;
        #pragma unroll
        for (int h = 0; h < 4; h++) {
            float p = Ssh[r * 5 + 1 + h] * inv + b1[h];
            hh[r][h] = 0.5f * p * (1.f + erff(p * k));
        }
    }
    __syncthreads();

    // ---- write: fc2/b2 loads amortized over the 4 rows ----
    int d = threadIdx.x * 4;
    float4 wa = ((const float4*)fc2)[d + 0];
    float4 wb = ((const float4*)fc2)[d + 1];
    float4 wc = ((const float4*)fc2)[d + 2];
    float4 wd = ((const float4*)fc2)[d + 3];
    float4 bz = ((const float4*)b2)[threadIdx.x];
    #pragma unroll
    for (int r = 0; r < RPB; r++) {
        if (!act[r]) continue;
        float h0 = hh[r][0], h1 = hh[r][1], h2 = hh[r][2], h3 = hh[r][3];
        float4 o;
        o.x = h0 * wa.x + h1 * wa.y + h2 * wa.z + h3 * wa.w + bz.x;
        o.y = h0 * wb.x + h1 * wb.y + h2 * wb.z + h3 * wb.w + bz.y;
        o.z = h0 * wc.x + h1 * wc.y + h2 * wc.z + h3 * wc.w + bz.z;
        o.w = h0 * wd.x + h1 * wd.y + h2 * wd.z + h3 * wd.w + bz.w;
        ((float4*)(cross + ((size_t)b * SQ + row0 + r) * D_EMB))[threadIdx.x] = o;
    }
}

// ---------------- classic softmax (self path): fp32 in -> fp16 probs --------
__global__ void softmax_kernel(const float* __restrict__ S, __half* __restrict__ P,
                               int n, int np, int sq, int rowp) {
    extern __shared__ float buf[];
    __shared__ float red[8];
    int b = blockIdx.x / sq, r = blockIdx.x % sq;
    const float* src = S + ((size_t)b * rowp + r) * np;
    __half* dst = P + ((size_t)b * rowp + r) * np;
    float m = -INFINITY;
    for (int i = threadIdx.x; i < n; i += 256) { float v = src[i]; buf[i] = v; m = fmaxf(m, v); }
    m = block_max(m, red);
    float s = 0.f;
    for (int i = threadIdx.x; i < n; i += 256) { float e = __expf(buf[i] - m); buf[i] = e; s += e; }
    s = block_sum(s, red);
    float inv = 1.f / s;
    for (int i = threadIdx.x; i < n; i += 256) dst[i] = __float2half_rn(buf[i] * inv);
    for (int i = n + threadIdx.x; i < np; i += 256) dst[i] = __ushort_as_half(0);
}

// ---------------- cp.async helper -------------------------------------------
__device__ __forceinline__ void cp16(void* dst, const void* src, bool pred) {
    uint32_t d = (uint32_t)__cvta_generic_to_shared(dst);
    int sz = pred ? 16 : 0;
    asm volatile("cp.async.cg.shared.global [%0], [%1], 16, %2;\n" :: "r"(d), "l"(src), "r"(sz));
}

// ---------------- QK GEMM: NT fp16 wmma, 128x128x64, 3-stage ----------------
#define QK_SMEM (3 * (128 * 72 + 128 * 72) * 2)
__global__ __launch_bounds__(256)
void gemm_qk(const __half* __restrict__ A, const __half* __restrict__ B, float* __restrict__ C,
             int Mreal, int Nreal, int K, int ldc,
             size_t sA, size_t sB, size_t sC, float alpha) {
    constexpr int ALD = 72;
    constexpr int ASZ = 128 * ALD;
    constexpr int STAGE = 2 * ASZ;

    extern __shared__ __half smh[];

    A += blockIdx.z * sA;  B += blockIdx.z * sB;  C += blockIdx.z * sC;
    const int m0 = blockIdx.x * 128, n0 = blockIdx.y * 128;
    const int tid = threadIdx.x, warp = tid >> 5;
    const int wm = warp >> 1, wn = warp & 1;

    wmma::fragment<wmma::accumulator, 16, 16, 16, float> acc[2][4];
    #pragma unroll
    for (int i = 0; i < 2; i++)
        #pragma unroll
        for (int j = 0; j < 4; j++) wmma::fill_fragment(acc[i][j], 0.f);

    auto load_tile = [&](int kt, int bufi) {
        const int k0 = kt * 64;
        __half* as = smh + bufi * STAGE;
        __half* bs = as + ASZ;
        #pragma unroll
        for (int i = 0; i < 4; i++) {
            int idx = tid + i * 256;
            int r = idx >> 3, v = (idx & 7) * 8;
            int gr = m0 + r;
            cp16(as + r * ALD + v, A + (size_t)gr * K + k0 + v, gr < Mreal);
        }
        #pragma unroll
        for (int i = 0; i < 4; i++) {
            int idx = tid + i * 256;
            int r = idx >> 3, v = (idx & 7) * 8;
            int gn = n0 + r;
            cp16(bs + r * ALD + v, B + (size_t)gn * K + k0 + v, gn < Nreal);
        }
        asm volatile("cp.async.commit_group;\n");
    };

    const int KT = K / 64;
    load_tile(0, 0);
    if (KT > 1) load_tile(1, 1);

    for (int kt = 0; kt < KT; kt++) {
        if (kt + 1 < KT) asm volatile("cp.async.wait_group 1;\n");
        else             asm volatile("cp.async.wait_group 0;\n");
        __syncthreads();
        if (kt + 2 < KT) load_tile(kt + 2, (kt + 2) % 3);

        __half* as = smh + (kt % 3) * STAGE;
        __half* bs = as + ASZ;
        #pragma unroll
        for (int ks = 0; ks < 4; ks++) {
            wmma::fragment<wmma::matrix_a, 16, 16, 16, __half, wmma::row_major> af[2];
            #pragma unroll
            for (int i = 0; i < 2; i++)
                wmma::load_matrix_sync(af[i], as + (wm * 32 + i * 16) * ALD + ks * 16, ALD);
            #pragma unroll
            for (int j = 0; j < 4; j++) {
                wmma::fragment<wmma::matrix_b, 16, 16, 16, __half, wmma::col_major> bf;
                wmma::load_matrix_sync(bf, bs + (wn * 64 + j * 16) * ALD + ks * 16, ALD);
                #pragma unroll
                for (int i = 0; i < 2; i++) wmma::mma_sync(acc[i][j], af[i], bf, acc[i][j]);
            }
        }
    }

    #pragma unroll
    for (int i = 0; i < 2; i++)
        #pragma unroll
        for (int j = 0; j < 4; j++) {
            #pragma unroll
            for (int e = 0; e < 8; e++) acc[i][j].x[e] *= alpha;
            int rg = m0 + wm * 32 + i * 16, cg = n0 + wn * 64 + j * 16;
            wmma::store_matrix_sync(C + (size_t)rg * ldc + cg, acc[i][j], ldc, wmma::mem_row_major);
        }
}

// ---------------- PV GEMM (self path): NN fp16 wmma, 128x256x32, 4-stage ----
#define PV_SMEM (4 * (128 * 40 + 32 * 264) * 2)
__global__ __launch_bounds__(256)
void gemm_pv(const __half* __restrict__ A, const __half* __restrict__ B, float* __restrict__ C,
             int Mreal, int K, int Kreal, int ldb_n, int ldc,
             size_t sA, size_t sB, size_t sC) {
    constexpr int BN = 256;
    constexpr int ALD = 40;
    constexpr int ASZ = 128 * ALD;
    constexpr int BLDN = BN + 8;
    constexpr int BSZ = 32 * BLDN;
    constexpr int STAGE = ASZ + BSZ;
    constexpr int NS = 4;

    extern __shared__ __half smh[];

    A += blockIdx.z * sA;  B += blockIdx.z * sB;  C += blockIdx.z * sC;
    const int m0 = blockIdx.x * 128, n0 = blockIdx.y * BN;
    const int tid = threadIdx.x, warp = tid >> 5;
    const int wm = warp >> 2, wn = warp & 3;

    wmma::fragment<wmma::accumulator, 16, 16, 16, float> acc[4][4];
    #pragma unroll
    for (int i = 0; i < 4; i++)
        #pragma unroll
        for (int j = 0; j < 4; j++) wmma::fill_fragment(acc[i][j], 0.f);

    auto load_tile = [&](int kt, int bufi) {
        const int k0 = kt * 32;
        __half* as = smh + bufi * STAGE;
        __half* bs = as + ASZ;
        #pragma unroll
        for (int i = 0; i < 2; i++) {
            int idx = tid + i * 256;
            int r = idx >> 2, v = (idx & 3) * 8;
            int gr = m0 + r;
            cp16(as + r * ALD + v, A + (size_t)gr * K + k0 + v, gr < Mreal);
        }
        #pragma unroll
        for (int i = 0; i < 4; i++) {
            int idx = tid + i * 256;
            int kk = idx >> 5, v = (idx & 31) * 8;
            int gk = k0 + kk;
            cp16(bs + kk * BLDN + v, B + (size_t)gk * ldb_n + n0 + v, gk < Kreal);
        }
        asm volatile("cp.async.commit_group;\n");
    };

    const int KT = K / 32;
    load_tile(0, 0);
    load_tile(1, 1);
    load_tile(2, 2);

    for (int kt = 0; kt < KT; kt++) {
        const int pend = KT - kt - 1;
        if (pend >= 2)      asm volatile("cp.async.wait_group 2;\n");
        else if (pend == 1) asm volatile("cp.async.wait_group 1;\n");
        else                asm volatile("cp.async.wait_group 0;\n");
        __syncthreads();
        if (kt + 3 < KT) load_tile(kt + 3, (kt + 3) % NS);

        __half* as = smh + (kt % NS) * STAGE;
        __half* bs = as + ASZ;
        #pragma unroll
        for (int ks = 0; ks < 2; ks++) {
            wmma::fragment<wmma::matrix_a, 16, 16, 16, __half, wmma::row_major> af[4];
            #pragma unroll
            for (int i = 0; i < 4; i++)
                wmma::load_matrix_sync(af[i], as + (wm * 64 + i * 16) * ALD + ks * 16, ALD);
            #pragma unroll
            for (int j = 0; j < 4; j++) {
                wmma::fragment<wmma::matrix_b, 16, 16, 16, __half, wmma::row_major> bf;
                wmma::load_matrix_sync(bf, bs + ks * 16 * BLDN + wn * 64 + j * 16, BLDN);
                #pragma unroll
                for (int i = 0; i < 4; i++) wmma::mma_sync(acc[i][j], af[i], bf, acc[i][j]);
            }
        }
    }

    #pragma unroll
    for (int i = 0; i < 4; i++)
        #pragma unroll
        for (int j = 0; j < 4; j++) {
            int rg = m0 + wm * 64 + i * 16, cg = n0 + wn * 64 + j * 16;
            wmma::store_matrix_sync(C + (size_t)rg * ldc + cg, acc[i][j], ldc, wmma::mem_row_major);
        }
}

// ---------------- final combine ---------------------------------------------
__global__ void final_kernel(const float* __restrict__ normQ, const float* __restrict__ cross,
                             const float* __restrict__ selfa, const float* __restrict__ g1,
                             const float* __restrict__ g2, float* __restrict__ out) {
    int b = blockIdx.x / SQ, r = blockIdx.x % SQ;
    size_t ci = ((size_t)b * SQ + r) * 256 + threadIdx.x;
    size_t si = ((size_t)b * ROWP + r) * 256 + threadIdx.x;
    float4 q = ((const float4*)normQ)[ci];
    float4 c = ((const float4*)cross)[ci];
    float4 s = ((const float4*)selfa)[si];
    float4 a = ((const float4*)g1)[threadIdx.x];
    float4 bb = ((const float4*)g2)[threadIdx.x];
    float4 o;
    o.x = q.x + bb.x * (c.x + a.x * s.x);
    o.y = q.y + bb.y * (c.y + a.y * s.y);
    o.z = q.z + bb.z * (c.z + a.z * s.z);
    o.w = q.w + bb.w * (c.w + a.w * s.w);
    ((float4*)out)[ci] = o;
}

// ---------------- launch ------------------------------------------------------
extern "C" void kernel_launch(void* const* d_in, const int* in_sizes, int n_in,
                              void* d_out, int out_size) {
    const float* input_features = (const float*)d_in[0];
    const float* query_feature  = (const float*)d_in[1];
    const float* n1w = (const float*)d_in[2];
    const float* n1b = (const float*)d_in[3];
    const float* n2w = (const float*)d_in[4];
    const float* n2b = (const float*)d_in[5];
    const float* n3w = (const float*)d_in[6];
    const float* n3b = (const float*)d_in[7];
    const float* g1  = (const float*)d_in[8];
    const float* g2  = (const float*)d_in[9];
    const float* fc1w = (const float*)d_in[10];
    const float* fc1b = (const float*)d_in[11];
    const float* fc2w = (const float*)d_in[12];
    const float* fc2b = (const float*)d_in[13];

    __half *normX_h, *normQ_h, *normC_h, *P2;
    float *xfp, *normQ, *S, *cross, *S2, *selfa;
    cudaGetSymbolAddress((void**)&normX_h, g_normX_h);
    cudaGetSymbolAddress((void**)&xfp,     g_xfp);
    cudaGetSymbolAddress((void**)&normQ,   g_normQ);
    cudaGetSymbolAddress((void**)&normQ_h, g_normQ_h);
    cudaGetSymbolAddress((void**)&S,       g_S);
    cudaGetSymbolAddress((void**)&cross,   g_cross);
    cudaGetSymbolAddress((void**)&normC_h, g_normC_h);
    cudaGetSymbolAddress((void**)&S2,      g_S2);
    cudaGetSymbolAddress((void**)&P2,      g_P2);
    cudaGetSymbolAddress((void**)&selfa,   g_self);

    cudaFuncSetAttribute((const void*)gemm_qk, cudaFuncAttributeMaxDynamicSharedMemorySize, QK_SMEM);
    cudaFuncSetAttribute((const void*)gemm_pv, cudaFuncAttributeMaxDynamicSharedMemorySize, PV_SMEM);
    cudaFuncSetAttribute((const void*)softmax_kernel, cudaFuncAttributeMaxDynamicSharedMemorySize, SQP * 4);

    const float scale = 0.03125f;   // 1024^-0.5

    // 1) layernorms (normX also emits planar Xf = LN(X) @ fc1^T)
    ln_kernel<<<NB * SK, 256>>>(input_features, n1w, n1b, normX_h, nullptr, fc1w, xfp);
    ln_kernel<<<NB * SQ, 256>>>(query_feature,  n2w, n2b, normQ_h, normQ, nullptr, nullptr);

    // 2) cross attention scores
    gemm_qk<<<dim3(ROWP / 128, SKP / 128, NB), 256, QK_SMEM>>>(
        normQ_h, normX_h, S, SQ, SK, D_EMB, SKP,
        (size_t)SQ * D_EMB, (size_t)SK * D_EMB, (size_t)ROWP * SKP, scale);

    // 3) fused ONLINE softmax + MLP -> cross_attended (4 rows/block)
    softmax_mlp_kernel<<<NB * RBLK, 256>>>(S, xfp, fc1b, fc2w, fc2b, cross);

    // 4) LN(cross) + self attention
    ln_kernel<<<NB * SQ, 256>>>(cross, n3w, n3b, normC_h, nullptr, nullptr, nullptr);
    gemm_qk<<<dim3(ROWP / 128, SQP / 128, NB), 256, QK_SMEM>>>(
        normC_h, normC_h, S2, SQ, SQ, D_EMB, SQP,
        (size_t)SQ * D_EMB, (size_t)SQ * D_EMB, (size_t)ROWP * SQP, scale);
    softmax_kernel<<<NB * SQ, 256, SQP * 4>>>(S2, P2, SQ, SQP, SQ, ROWP);
    gemm_pv<<<dim3(ROWP / 128, D_EMB / 256, NB), 256, PV_SMEM>>>(
        P2, normC_h, selfa, SQ, SQP, SQ, D_EMB, D_EMB,
        (size_t)ROWP * SQP, (size_t)SQ * D_EMB, (size_t)ROWP * D_EMB);

    // 5) combine
    final_kernel<<<NB * SQ, 256>>>(normQ, cross, selfa, g1, g2, (float*)d_out);
}